// round 15
// speedup vs baseline: 5.7252x; 1.0083x over previous
#include <cuda_runtime.h>
#include <cuda_fp16.h>
#include <math.h>
#include <stdint.h>

// Problem constants
#define SEQ   4096
#define EMBD  2048
#define NB    4
#define NHEAD 16
#define DHEAD 128
#define NSEG  8
#define SEGL  512
#define NBH   (NB * NHEAD)          // 64
#define MTOK  (NB * SEQ)            // 16384
#define TOTAL ((size_t)MTOK * EMBD) // 33554432
#define EMBD_U (EMBD / 2)           // 1024 u32 per row
#define SEGL_U (SEGL / 2)           // 256

// -------- device scratch ----------------------------------------------------
__device__ float g_memsegT[(size_t)NBH * NSEG * DHEAD * DHEAD]; // mem^T [e][d]
__device__ float g_Zseg[NBH * NSEG * DHEAD];
__device__ uint32_t g_Wth[(size_t)4 * EMBD * EMBD_U]; // transposed+permuted fp16
__device__ uint32_t g_xh[TOTAL / 2];                  // permuted fp16 x
__device__ uint32_t g_attnh[TOTAL / 2];               // permuted fp16 attn
__device__ uint32_t g_qh[TOTAL / 2];                  // fp16 q (pairs along d, roped)
__device__ uint32_t g_kh[TOTAL / 2];                  // fp16 k (pairs along d, roped)
__device__ uint32_t g_vh[TOTAL / 2];                  // fp16 v (pairs along d)
__device__ uint32_t g_vth[(size_t)NBH * NSEG * DHEAD * SEGL_U]; // fp16 v^T
__device__ uint32_t g_skth[(size_t)NBH * NSEG * DHEAD * SEGL_U]; // fp16 sk^T
__device__ float g_cost[(size_t)SEQ * 1024];          // rope cos table
__device__ float g_sint[(size_t)SEQ * 1024];          // rope sin table

__device__ __forceinline__ float elu1(float x) {
    return (x > 0.f) ? (x + 1.f) : expf(x);
}

__device__ __forceinline__ uint32_t smem_u32(const void* p) {
    uint32_t a;
    asm("{ .reg .u64 t; cvta.to.shared.u64 t, %1; cvt.u32.u64 %0, t; }"
        : "=r"(a) : "l"(p));
    return a;
}

__device__ __forceinline__ void cp16(uint32_t saddr, const void* g) {
    asm volatile("cp.async.cg.shared.global [%0], [%1], 16;" :: "r"(saddr), "l"(g));
}

__device__ __forceinline__ uint32_t f2tf32(float x) {
    uint32_t u;
    asm("cvt.rna.tf32.f32 %0, %1;" : "=r"(u) : "f"(x));
    return u;
}

__device__ __forceinline__ uint32_t packh2(float lo, float hi) {
    __half2 h = __floats2half2_rn(lo, hi);
    return *(uint32_t*)&h;
}

__device__ __forceinline__ void mma_tf32(float* d, const uint32_t* a, const uint32_t* b) {
    asm volatile(
        "mma.sync.aligned.m16n8k8.row.col.f32.tf32.tf32.f32 "
        "{%0,%1,%2,%3}, {%4,%5,%6,%7}, {%8,%9}, {%0,%1,%2,%3};"
        : "+f"(d[0]), "+f"(d[1]), "+f"(d[2]), "+f"(d[3])
        : "r"(a[0]), "r"(a[1]), "r"(a[2]), "r"(a[3]), "r"(b[0]), "r"(b[1]));
}

__device__ __forceinline__ void mma_f16(float* d, const uint32_t* a, const uint32_t* b) {
    asm volatile(
        "mma.sync.aligned.m16n8k16.row.col.f32.f16.f16.f32 "
        "{%0,%1,%2,%3}, {%4,%5,%6,%7}, {%8,%9}, {%0,%1,%2,%3};"
        : "+f"(d[0]), "+f"(d[1]), "+f"(d[2]), "+f"(d[3])
        : "r"(a[0]), "r"(a[1]), "r"(a[2]), "r"(a[3]), "r"(b[0]), "r"(b[1]));
}

__device__ __forceinline__ int pposu(int j) { return (j < 4) ? 2 * j : 2 * (j - 4) + 1; }

// ============================================================================
// K0a: transpose + u32-permute + fp16 convert of ALL 4 weights (blockIdx.z)
// ============================================================================
__global__ __launch_bounds__(256) void transpose_fp16_all_k(
    const float* __restrict__ Wq, const float* __restrict__ Wk,
    const float* __restrict__ Wv, const float* __restrict__ Wo,
    uint32_t* __restrict__ WthBase)
{
    __shared__ float t[32][33];
    int z = blockIdx.z;
    const float* W = (z == 0) ? Wq : (z == 1) ? Wk : (z == 2) ? Wv : Wo;
    uint32_t* Wth = WthBase + (size_t)z * EMBD * EMBD_U;
    int bx = blockIdx.x * 32, by = blockIdx.y * 32;
    int txx = threadIdx.x;
    for (int i = threadIdx.y; i < 32; i += 8)
        t[i][txx] = W[(size_t)(by + i) * EMBD + bx + txx];
    __syncthreads();
    if (txx < 16) {
        int j = txx & 7;
        int pos = (by >> 1) + (txx >> 3) * 8 + pposu(j);
        for (int i = threadIdx.y; i < 32; i += 8) {
            uint32_t u = packh2(t[2 * txx][i], t[2 * txx + 1][i]);
            Wth[(size_t)(bx + i) * EMBD_U + pos] = u;
        }
    }
}

// ============================================================================
// K0b: u32-permute + fp16 convert of x
// ============================================================================
__global__ __launch_bounds__(256) void perm_cvt_fp16_k(const float* __restrict__ src,
                                                       uint32_t* __restrict__ dst)
{
    size_t g16 = (size_t)blockIdx.x * 256 + threadIdx.x;
    size_t base = g16 * 16;
    float4 f0 = *(const float4*)&src[base];
    float4 f1 = *(const float4*)&src[base + 4];
    float4 f2 = *(const float4*)&src[base + 8];
    float4 f3 = *(const float4*)&src[base + 12];
    uint4 o0, o1;
    o0.x = packh2(f0.x, f0.y);
    o0.y = packh2(f2.x, f2.y);
    o0.z = packh2(f0.z, f0.w);
    o0.w = packh2(f2.z, f2.w);
    o1.x = packh2(f1.x, f1.y);
    o1.y = packh2(f3.x, f3.y);
    o1.z = packh2(f1.z, f1.w);
    o1.w = packh2(f3.z, f3.w);
    *(uint4*)&dst[g16 * 8] = o0;
    *(uint4*)&dst[g16 * 8 + 4] = o1;
}

// ============================================================================
// K0c: rope cos/sin tables
// ============================================================================
__global__ __launch_bounds__(256) void rope_tab_k(float* __restrict__ cost,
                                                  float* __restrict__ sint)
{
    size_t idx = (size_t)blockIdx.x * 256 + threadIdx.x;
    int t = (int)(idx >> 10);
    int i = (int)(idx & 1023);
    float inv = powf(10000.0f, -(float)(2 * i) * (1.0f / 2048.0f));
    float ang = (float)t * inv;
    cost[idx] = cosf(ang);
    sint[idx] = sinf(ang);
}

// ============================================================================
// K1: fp16 mma.sync GEMM mainloop (shared), CTA 128x256x32, 3-stage pipeline
// ============================================================================
#define BM 128
#define BN 256
#define BK 32
#define BKU 16
#define BKP_U 24
#define NSTG 3
#define STG_U ((BM + BN) * BKP_U)
#define GEMM_SMEM_BYTES (NSTG * STG_U * 4)

__device__ __forceinline__ void load_stage_h(const uint32_t* __restrict__ A,
                                             const uint32_t* __restrict__ Bt,
                                             int brow, int bcol, int k0u,
                                             uint32_t sA, uint32_t sB, int tid)
{
#pragma unroll
    for (int it = 0; it < 2; it++) {
        int idx = tid + it * 256;
        int row = idx >> 2, c4 = idx & 3;
        cp16(sA + (row * BKP_U + c4 * 4) * 4,
             A + (size_t)(brow + row) * EMBD_U + k0u + c4 * 4);
    }
#pragma unroll
    for (int it = 0; it < 4; it++) {
        int idx = tid + it * 256;
        int row = idx >> 2, c4 = idx & 3;
        cp16(sB + (row * BKP_U + c4 * 4) * 4,
             Bt + (size_t)(bcol + row) * EMBD_U + k0u + c4 * 4);
    }
    asm volatile("cp.async.commit_group;" ::: "memory");
}

__device__ __forceinline__ void gemm_mainloop(
    const uint32_t* __restrict__ A, const uint32_t* __restrict__ Bt,
    uint32_t* dsm_u, float acc[4][8][4], int brow, int bcol,
    int tid, int wm, int wn, int lr, int lc)
{
    uint32_t sbase = smem_u32(dsm_u);
    uint32_t sA[NSTG], sB[NSTG];
#pragma unroll
    for (int s = 0; s < NSTG; s++) {
        sA[s] = sbase + s * STG_U * 4;
        sB[s] = sA[s] + BM * BKP_U * 4;
    }

    load_stage_h(A, Bt, brow, bcol, 0 * BKU, sA[0], sB[0], tid);
    load_stage_h(A, Bt, brow, bcol, 1 * BKU, sA[1], sB[1], tid);
    load_stage_h(A, Bt, brow, bcol, 2 * BKU, sA[2], sB[2], tid);

    const int NIT = EMBD / BK;
    for (int it = 0; it < NIT; it++) {
        if (it < NIT - 2)       asm volatile("cp.async.wait_group 2;" ::: "memory");
        else if (it == NIT - 2) asm volatile("cp.async.wait_group 1;" ::: "memory");
        else                    asm volatile("cp.async.wait_group 0;" ::: "memory");
        __syncthreads();

        int s = it % NSTG;
        const uint32_t* As = dsm_u + (size_t)s * STG_U;
        const uint32_t* Bs = As + BM * BKP_U;

#pragma unroll
        for (int kc = 0; kc < 2; kc++) {
            int off = kc * 8 + 2 * lc;
            uint32_t af[4][4], bf[8][2];
#pragma unroll
            for (int mt = 0; mt < 4; mt++) {
                int r = wm + mt * 16 + lr;
                uint2 a0 = *(const uint2*)&As[r * BKP_U + off];
                uint2 a1 = *(const uint2*)&As[(r + 8) * BKP_U + off];
                af[mt][0] = a0.x; af[mt][2] = a0.y;
                af[mt][1] = a1.x; af[mt][3] = a1.y;
            }
#pragma unroll
            for (int nt = 0; nt < 8; nt++) {
                int cN = wn + nt * 8 + lr;
                uint2 b = *(const uint2*)&Bs[cN * BKP_U + off];
                bf[nt][0] = b.x; bf[nt][1] = b.y;
            }
#pragma unroll
            for (int mt = 0; mt < 4; mt++)
#pragma unroll
                for (int nt = 0; nt < 8; nt++)
                    mma_f16(acc[mt][nt], af[mt], bf[nt]);
        }
        __syncthreads();

        if (it + NSTG < NIT)
            load_stage_h(A, Bt, brow, bcol, (it + NSTG) * BKU, sA[s], sB[s], tid);
    }
}

// final GEMM: fp32 output + bias
__global__ __launch_bounds__(256) void gemm_mma_k(
    const uint32_t* __restrict__ A, const uint32_t* __restrict__ Bt,
    const float* __restrict__ bias, float* __restrict__ C)
{
    extern __shared__ uint32_t dsm_u[];
    const int tid = threadIdx.x;
    const int wid = tid >> 5;
    const int lane = tid & 31;
    const int lr = lane >> 2, lc = lane & 3;
    const int wm = (wid >> 2) * 64, wn = (wid & 3) * 64;
    int brow = blockIdx.y * BM, bcol = blockIdx.x * BN;

    float acc[4][8][4];
#pragma unroll
    for (int mt = 0; mt < 4; mt++)
#pragma unroll
        for (int nt = 0; nt < 8; nt++)
#pragma unroll
            for (int r = 0; r < 4; r++) acc[mt][nt][r] = 0.f;

    gemm_mainloop(A, Bt, dsm_u, acc, brow, bcol, tid, wm, wn, lr, lc);

#pragma unroll
    for (int nt = 0; nt < 8; nt++) {
        int col = bcol + wn + nt * 8 + 2 * lc;
        float b0 = bias[col], b1 = bias[col + 1];
#pragma unroll
        for (int mt = 0; mt < 4; mt++) {
            int row = brow + wm + mt * 16 + lr;
            float2 v0 = make_float2(acc[mt][nt][0] + b0, acc[mt][nt][1] + b1);
            float2 v1 = make_float2(acc[mt][nt][2] + b0, acc[mt][nt][3] + b1);
            *(float2*)&C[(size_t)row * EMBD + col] = v0;
            *(float2*)&C[(size_t)(row + 8) * EMBD + col] = v1;
        }
    }
}

// QKV GEMM: fused bias + rope (z<2) + fp16 pack
__global__ __launch_bounds__(256) void gemm_qkv_k(
    const uint32_t* __restrict__ A, const uint32_t* __restrict__ WtBase,
    const float* __restrict__ bq, const float* __restrict__ bk,
    const float* __restrict__ bv,
    uint32_t* __restrict__ qh, uint32_t* __restrict__ kh, uint32_t* __restrict__ vh,
    const float* __restrict__ cost, const float* __restrict__ sint)
{
    extern __shared__ uint32_t dsm_u[];
    const int tid = threadIdx.x;
    const int wid = tid >> 5;
    const int lane = tid & 31;
    const int lr = lane >> 2, lc = lane & 3;
    const int wm = (wid >> 2) * 64, wn = (wid & 3) * 64;
    int brow = blockIdx.y * BM, bcol = blockIdx.x * BN;

    int z = blockIdx.z;
    const uint32_t* Bt = WtBase + (size_t)z * EMBD * EMBD_U;
    const float* bias = (z == 0) ? bq : (z == 1) ? bk : bv;
    uint32_t* Ch = (z == 0) ? qh : (z == 1) ? kh : vh;
    bool dorope = (z < 2);

    float acc[4][8][4];
#pragma unroll
    for (int mt = 0; mt < 4; mt++)
#pragma unroll
        for (int nt = 0; nt < 8; nt++)
#pragma unroll
            for (int r = 0; r < 4; r++) acc[mt][nt][r] = 0.f;

    gemm_mainloop(A, Bt, dsm_u, acc, brow, bcol, tid, wm, wn, lr, lc);

#pragma unroll
    for (int nt = 0; nt < 8; nt++) {
        int col = bcol + wn + nt * 8 + 2 * lc;
        int pi = col >> 1;
        float b0 = bias[col], b1 = bias[col + 1];
#pragma unroll
        for (int mt = 0; mt < 4; mt++) {
#pragma unroll
            for (int h = 0; h < 2; h++) {
                int row = brow + wm + mt * 16 + lr + h * 8;
                float a0 = acc[mt][nt][2 * h + 0] + b0;
                float a1 = acc[mt][nt][2 * h + 1] + b1;
                if (dorope) {
                    int t = row & (SEQ - 1);
                    float c = cost[(size_t)t * 1024 + pi];
                    float s = sint[(size_t)t * 1024 + pi];
                    float r0 = a0 * c - a1 * s;
                    float r1 = a0 * s + a1 * c;
                    a0 = r0; a1 = r1;
                }
                Ch[(size_t)row * EMBD_U + pi] = packh2(a0, a1);
            }
        }
    }
}

// ============================================================================
// K2b: merged v^T / sk^T transposes (blockIdx.y parity selects path)
// ============================================================================
__global__ __launch_bounds__(256) void vtskt_k(const uint32_t* __restrict__ vh,
                                               const uint32_t* __restrict__ kh,
                                               uint32_t* __restrict__ vth,
                                               uint32_t* __restrict__ skth)
{
    __shared__ float t[32][68];
    int bhs = blockIdx.z;
    int p0 = blockIdx.x * 32;
    int which = blockIdx.y & 1;               // 0 = v, 1 = sk
    int l0 = (blockIdx.y >> 1) * 32;
    const uint32_t* seg = (which ? kh : vh) + ((size_t)bhs << 15);
    uint32_t* dst = (which ? skth : vth) + (size_t)bhs * DHEAD * SEGL_U;
    int txx = threadIdx.x, ty = threadIdx.y;
    for (int i = ty; i < 32; i += 8) {
        __half2 h = *(const __half2*)&seg[(size_t)(l0 + i) * 64 + p0 + txx];
        t[i][2 * txx] = __low2float(h);
        t[i][2 * txx + 1] = __high2float(h);
    }
    __syncthreads();
    int tid = ty * 32 + txx;
#pragma unroll
    for (int j = 0; j < 4; j++) {
        int flat = tid + j * 256;
        int d = flat >> 4, c = flat & 15;
        float a = t[2 * c][d], b = t[2 * c + 1][d];
        if (which) { a = elu1(a); b = elu1(b); }
        dst[(size_t)(2 * p0 + d) * SEGL_U + (l0 >> 1) + c] = packh2(a, b);
    }
}

// ============================================================================
// K2d: Zseg[bhs][d] = row-sum of skth
// ============================================================================
__global__ __launch_bounds__(256) void zsum_k(const uint32_t* __restrict__ skth,
                                              float* __restrict__ Zseg)
{
    int bhs = blockIdx.x;
    int tid = threadIdx.x;
    int d = tid >> 1;
    int half = tid & 1;
    const uint32_t* row = skth + (size_t)bhs * DHEAD * SEGL_U
                        + (size_t)d * SEGL_U + half * 128;
    float s = 0.f;
#pragma unroll 16
    for (int j = 0; j < 128; j++) {
        __half2 h = *(const __half2*)&row[j];
        s += __low2float(h) + __high2float(h);
    }
    s += __shfl_xor_sync(0xffffffffu, s, 1);
    if (half == 0) Zseg[bhs * DHEAD + d] = s;
}

// ============================================================================
// K3: FUSED flash attention + A_mem + combine, with pipelined k/v prefetch
// ============================================================================
#define SCP 68
#define AMP 136
// u32 layout: qs[0,8704) | ks[8704,17408) | Ps[17408,26112) | vs0[26112,34816)
//             vs1[34816,43520) ; aq overlays ks+Ps ; ms overlays vs0+vs1
#define FAM_U32 (43520 + 1536)
#define FAM_SMEM_BYTES (FAM_U32 * 4)   // 180224

__global__ __launch_bounds__(256, 1) void fam_k(
    const uint32_t* __restrict__ qh, const uint32_t* __restrict__ kh,
    const uint32_t* __restrict__ vth, const float* __restrict__ memsegT,
    const float* __restrict__ Zseg, const float* __restrict__ beta,
    uint32_t* __restrict__ attnh)
{
    extern __shared__ uint32_t smu[];
    uint32_t* qs = smu;                       // [128][SCP] fp16 q
    uint32_t* ks = smu + 128 * SCP;           // flash k tile (prefetched)
    uint32_t* Ps = smu + 2 * 128 * SCP;       // flash P tile
    uint32_t* vsb[2] = { smu + 3 * 128 * SCP, smu + 4 * 128 * SCP }; // v double buf
    uint32_t* aq = smu + 128 * SCP;           // amem: tf32 elu1(q) (over ks+Ps)
    uint32_t* ms = smu + 3 * 128 * SCP;       // amem: tf32 memT (over vs0+vs1)
    float* pmax = (float*)(smu + 43520);
    float* psum = pmax + 4 * 128;
    float* m_s = psum + 4 * 128;
    float* f_s = m_s + 128;
    float* ssum_s = f_s + 128;
    float* Zs = ssum_s + 128;

    uint32_t sq = smem_u32(qs);
    uint32_t sk = smem_u32(ks);
    uint32_t sv0 = smem_u32(vsb[0]);
    uint32_t sv1 = smem_u32(vsb[1]);
    uint32_t smb = smem_u32(ms);

    const float scale = 0.08838834764831845f;
    const int tid = threadIdx.x;
    const int wid = tid >> 5;
    const int lane = tid & 31;
    const int lr = lane >> 2;
    const int lc = lane & 3;
    const int wm = (wid >> 2) * 64;
    const int wn = (wid & 3) * 32;
    const int wci = wid & 3;

    int bhs = blockIdx.y;
    int l0 = blockIdx.x * 128;
    size_t segbase_u = ((size_t)bhs) << 15;
    const uint32_t* qseg = qh + segbase_u;
    const uint32_t* kseg = kh + segbase_u;
    const uint32_t* vtseg = vth + (size_t)bhs * DHEAD * SEGL_U;
    const float* memb = memsegT + (size_t)bhs * DHEAD * DHEAD;
    float g = 1.0f / (1.0f + expf(-beta[0]));
    float gm1 = 1.0f - g;

    // prologue loads: q tile, k0, v0 — one group
#pragma unroll
    for (int it = 0; it < 8; it++) {
        int idx = tid + it * 256;
        int row = idx >> 4, c4 = idx & 15;
        cp16(sq + (row * SCP + c4 * 4) * 4,
             qseg + (size_t)(l0 + row) * 64 + c4 * 4);
    }
#pragma unroll
    for (int it = 0; it < 8; it++) {
        int idx = tid + it * 256;
        int row = idx >> 4, c4 = idx & 15;
        cp16(sk + (row * SCP + c4 * 4) * 4,
             kseg + (size_t)row * 64 + c4 * 4);
    }
#pragma unroll
    for (int it = 0; it < 8; it++) {
        int idx = tid + it * 256;
        int row = idx >> 4, c4 = idx & 15;
        cp16(sv0 + (row * SCP + c4 * 4) * 4,
             vtseg + (size_t)row * SEGL_U + c4 * 4);
    }
    asm volatile("cp.async.commit_group;" ::: "memory");

    if (tid < 128) { m_s[tid] = -1e30f; ssum_s[tid] = 0.f; }

    float Oacc[4][4][4];
#pragma unroll
    for (int mt = 0; mt < 4; mt++)
#pragma unroll
        for (int nt = 0; nt < 4; nt++)
#pragma unroll
            for (int r = 0; r < 4; r++) Oacc[mt][nt][r] = 0.f;

    // ---------------- flash phase (pipelined k/v prefetch) ----------------
    for (int kt = 0; kt < 4; kt++) {
        uint32_t* vs = vsb[kt & 1];
        asm volatile("cp.async.wait_group 0;" ::: "memory");
        __syncthreads();

        float Sacc[4][4][4];
#pragma unroll
        for (int mt = 0; mt < 4; mt++)
#pragma unroll
            for (int nt = 0; nt < 4; nt++)
#pragma unroll
                for (int r = 0; r < 4; r++) Sacc[mt][nt][r] = 0.f;

#pragma unroll
        for (int kb = 0; kb < 64; kb += 8) {
            uint32_t af[4][4], bf[4][2];
#pragma unroll
            for (int mt = 0; mt < 4; mt++) {
                int r = wm + mt * 16 + lr;
                af[mt][0] = qs[r * SCP + kb + lc];
                af[mt][1] = qs[(r + 8) * SCP + kb + lc];
                af[mt][2] = qs[r * SCP + kb + lc + 4];
                af[mt][3] = qs[(r + 8) * SCP + kb + lc + 4];
            }
#pragma unroll
            for (int nt = 0; nt < 4; nt++) {
                int cN = wn + nt * 8 + lr;
                bf[nt][0] = ks[cN * SCP + kb + lc];
                bf[nt][1] = ks[cN * SCP + kb + lc + 4];
            }
#pragma unroll
            for (int mt = 0; mt < 4; mt++)
#pragma unroll
                for (int nt = 0; nt < 4; nt++)
                    mma_f16(Sacc[mt][nt], af[mt], bf[nt]);
        }
#pragma unroll
        for (int mt = 0; mt < 4; mt++)
#pragma unroll
            for (int nt = 0; nt < 4; nt++)
#pragma unroll
                for (int r = 0; r < 4; r++) Sacc[mt][nt][r] *= scale;

#pragma unroll
        for (int mt = 0; mt < 4; mt++) {
#pragma unroll
            for (int h = 0; h < 2; h++) {
                float mv = -1e30f;
#pragma unroll
                for (int nt = 0; nt < 4; nt++) {
                    mv = fmaxf(mv, Sacc[mt][nt][2 * h]);
                    mv = fmaxf(mv, Sacc[mt][nt][2 * h + 1]);
                }
                mv = fmaxf(mv, __shfl_xor_sync(0xffffffffu, mv, 1));
                mv = fmaxf(mv, __shfl_xor_sync(0xffffffffu, mv, 2));
                if (lc == 0) pmax[wci * 128 + wm + mt * 16 + lr + h * 8] = mv;
            }
        }
        __syncthreads();
        // all warps are past S-mma: safe to prefetch next k into ks and next v
        if (kt < 3) {
            uint32_t svn = (kt & 1) ? sv0 : sv1;
#pragma unroll
            for (int it = 0; it < 8; it++) {
                int idx = tid + it * 256;
                int row = idx >> 4, c4 = idx & 15;
                cp16(sk + (row * SCP + c4 * 4) * 4,
                     kseg + (size_t)((kt + 1) * 128 + row) * 64 + c4 * 4);
            }
#pragma unroll
            for (int it = 0; it < 8; it++) {
                int idx = tid + it * 256;
                int row = idx >> 4, c4 = idx & 15;
                cp16(svn + (row * SCP + c4 * 4) * 4,
                     vtseg + (size_t)row * SEGL_U + (kt + 1) * 64 + c4 * 4);
            }
            asm volatile("cp.async.commit_group;" ::: "memory");
        }

        if (tid < 128) {
            float mo = m_s[tid];
            float nm = fmaxf(fmaxf(pmax[tid], pmax[128 + tid]),
                             fmaxf(pmax[256 + tid], pmax[384 + tid]));
            float mn = fmaxf(mo, nm);
            float f = expf(mo - mn);
            m_s[tid] = mn;
            f_s[tid] = f;
            ssum_s[tid] *= f;
        }
        __syncthreads();

#pragma unroll
        for (int mt = 0; mt < 4; mt++) {
#pragma unroll
            for (int h = 0; h < 2; h++) {
                int row = wm + mt * 16 + lr + h * 8;
                float m = m_s[row];
                float f = f_s[row];
                float rsum = 0.f;
#pragma unroll
                for (int nt = 0; nt < 4; nt++) {
                    float p0 = expf(Sacc[mt][nt][2 * h] - m);
                    float p1 = expf(Sacc[mt][nt][2 * h + 1] - m);
                    rsum += p0 + p1;
                    Ps[row * SCP + (wn >> 1) + nt * 4 + lc] = packh2(p0, p1);
                    Oacc[mt][nt][2 * h] *= f;
                    Oacc[mt][nt][2 * h + 1] *= f;
                }
                rsum += __shfl_xor_sync(0xffffffffu, rsum, 1);
                rsum += __shfl_xor_sync(0xffffffffu, rsum, 2);
                if (lc == 0) psum[wci * 128 + row] = rsum;
            }
        }
        __syncthreads();

        if (tid < 128)
            ssum_s[tid] += psum[tid] + psum[128 + tid] + psum[256 + tid] + psum[384 + tid];

#pragma unroll
        for (int kb = 0; kb < 64; kb += 8) {
            uint32_t af[4][4], bf[4][2];
#pragma unroll
            for (int mt = 0; mt < 4; mt++) {
                int r = wm + mt * 16 + lr;
                af[mt][0] = Ps[r * SCP + kb + lc];
                af[mt][1] = Ps[(r + 8) * SCP + kb + lc];
                af[mt][2] = Ps[r * SCP + kb + lc + 4];
                af[mt][3] = Ps[(r + 8) * SCP + kb + lc + 4];
            }
#pragma unroll
            for (int nt = 0; nt < 4; nt++) {
                int cN = wn + nt * 8 + lr;
                bf[nt][0] = vs[cN * SCP + kb + lc];
                bf[nt][1] = vs[cN * SCP + kb + lc + 4];
            }
#pragma unroll
            for (int mt = 0; mt < 4; mt++)
#pragma unroll
                for (int nt = 0; nt < 4; nt++)
                    mma_f16(Oacc[mt][nt], af[mt], bf[nt]);
        }
        __syncthreads();
    }

    // ---------------- amem phase (aq over ks/Ps, ms over vs0+vs1) ----------
#pragma unroll
    for (int it = 0; it < 16; it++) {
        int idx = tid + it * 256;
        int row = idx >> 5, c4 = idx & 31;
        cp16(smb + (row * AMP + c4 * 4) * 4,
             memb + (size_t)row * DHEAD + c4 * 4);
    }
    asm volatile("cp.async.commit_group;" ::: "memory");

#pragma unroll
    for (int it = 0; it < 32; it++) {
        int flat = it * 256 + tid;
        int row = flat >> 6, col = flat & 63;
        __half2 h = *(const __half2*)&qs[row * SCP + col];
        aq[row * AMP + 2 * col]     = f2tf32(elu1(__low2float(h)));
        aq[row * AMP + 2 * col + 1] = f2tf32(elu1(__high2float(h)));
    }
    asm volatile("cp.async.wait_group 0;" ::: "memory");
    __syncthreads();

    {
        int r = tid >> 1;
        int half = (tid & 1) * 64;
        float partial = 0.f;
#pragma unroll 16
        for (int j = 0; j < 64; j++)
            partial += __uint_as_float(aq[r * AMP + half + j]);
        partial += __shfl_xor_sync(0xffffffffu, partial, 1);
        if ((tid & 1) == 0) pmax[r] = partial;   // reuse pmax as rowsum
#pragma unroll 16
        for (int j = 0; j < 64; j++) {
            uint32_t* p = &ms[r * AMP + half + j];
            *p = f2tf32(__uint_as_float(*p));
        }
    }
    if (tid < 128) Zs[tid] = Zseg[bhs * DHEAD + tid];
    __syncthreads();

    float acc[4][4][4];
#pragma unroll
    for (int mt = 0; mt < 4; mt++)
#pragma unroll
        for (int nt = 0; nt < 4; nt++)
#pragma unroll
            for (int r = 0; r < 4; r++) acc[mt][nt][r] = 0.f;

#pragma unroll
    for (int kb = 0; kb < 128; kb += 8) {
        uint32_t af[4][4], bf[4][2];
#pragma unroll
        for (int mt = 0; mt < 4; mt++) {
            int r = wm + mt * 16 + lr;
            af[mt][0] = aq[r * AMP + kb + lc];
            af[mt][1] = aq[(r + 8) * AMP + kb + lc];
            af[mt][2] = aq[r * AMP + kb + lc + 4];
            af[mt][3] = aq[(r + 8) * AMP + kb + lc + 4];
        }
#pragma unroll
        for (int nt = 0; nt < 4; nt++) {
            int cN = wn + nt * 8 + lr;
            bf[nt][0] = ms[cN * AMP + kb + lc];
            bf[nt][1] = ms[cN * AMP + kb + lc + 4];
        }
#pragma unroll
        for (int mt = 0; mt < 4; mt++)
#pragma unroll
            for (int nt = 0; nt < 4; nt++)
                mma_tf32(acc[mt][nt], af[mt], bf[nt]);
    }

#pragma unroll
    for (int nt = 0; nt < 4; nt++) {
        int col = wn + nt * 8 + 2 * lc;
        int j = (col & 15) >> 1;
        int pos = (col >> 4) * 8 + pposu(j);
        float Z0 = Zs[col], Z1 = Zs[col + 1];
#pragma unroll
        for (int mt = 0; mt < 4; mt++) {
#pragma unroll
            for (int h = 0; h < 2; h++) {
                int rloc = wm + mt * 16 + lr + h * 8;
                int row = l0 + rloc;
                float rs = pmax[rloc];             // rowsum
                float sc = gm1 / ssum_s[rloc];
                float a0 = g * acc[mt][nt][2 * h + 0] / (rs * Z0 + 1e-6f)
                         + Oacc[mt][nt][2 * h + 0] * sc;
                float a1 = g * acc[mt][nt][2 * h + 1] / (rs * Z1 + 1e-6f)
                         + Oacc[mt][nt][2 * h + 1] * sc;
                attnh[segbase_u + (size_t)row * (DHEAD / 2) + pos] = packh2(a0, a1);
            }
        }
    }
}

// ============================================================================
// K6: tensorized outer products: memT[e][d] = sum_l v[l][e] * sk[l][d]
// ============================================================================
#define PVP 36
#define OUTER_SMEM_BYTES (2 * 2 * 128 * PVP * 4)

__global__ __launch_bounds__(256) void outer_mma_k(
    const uint32_t* __restrict__ vth, const uint32_t* __restrict__ skth,
    float* __restrict__ memsegT)
{
    extern __shared__ uint32_t smu[];
    uint32_t* Ash = smu;
    uint32_t* Bsh = smu + 2 * 128 * PVP;
    uint32_t sAu = smem_u32(Ash);
    uint32_t sBu = smem_u32(Bsh);

    const int tid = threadIdx.x;
    const int wid = tid >> 5;
    const int lane = tid & 31;
    const int lr = lane >> 2;
    const int lc = lane & 3;
    const int wm = (wid >> 2) * 64;
    const int wn = (wid & 3) * 32;

    int bhs = blockIdx.x;
    const uint32_t* vtseg = vth + (size_t)bhs * DHEAD * SEGL_U;
    const uint32_t* sktseg = skth + (size_t)bhs * DHEAD * SEGL_U;

    float acc[4][4][4];
#pragma unroll
    for (int mt = 0; mt < 4; mt++)
#pragma unroll
        for (int nt = 0; nt < 4; nt++)
#pragma unroll
            for (int r = 0; r < 4; r++) acc[mt][nt][r] = 0.f;

    auto load_st = [&](int k0u, uint32_t sA, uint32_t sB) {
#pragma unroll
        for (int it = 0; it < 4; it++) {
            int idx = tid + it * 256;
            int row = idx >> 3, c4 = idx & 7;
            cp16(sA + (row * PVP + c4 * 4) * 4,
                 vtseg + (size_t)row * SEGL_U + k0u + c4 * 4);
        }
#pragma unroll
        for (int it = 0; it < 4; it++) {
            int idx = tid + it * 256;
            int row = idx >> 3, c4 = idx & 7;
            cp16(sB + (row * PVP + c4 * 4) * 4,
                 sktseg + (size_t)row * SEGL_U + k0u + c4 * 4);
        }
        asm volatile("cp.async.commit_group;" ::: "memory");
    };

    load_st(0, sAu, sBu);
    load_st(32, sAu + 128 * PVP * 4, sBu + 128 * PVP * 4);

    const int NIT = SEGL_U / 32;
    for (int it = 0; it < NIT; it++) {
        int s = it & 1;
        if (it == NIT - 1) asm volatile("cp.async.wait_group 0;" ::: "memory");
        else               asm volatile("cp.async.wait_group 1;" ::: "memory");
        __syncthreads();

        const uint32_t* As = Ash + s * 128 * PVP;
        const uint32_t* Bs = Bsh + s * 128 * PVP;
#pragma unroll
        for (int kb = 0; kb < 32; kb += 8) {
            uint32_t af[4][4], bf[4][2];
#pragma unroll
            for (int mt = 0; mt < 4; mt++) {
                int r = wm + mt * 16 + lr;
                af[mt][0] = As[r * PVP + kb + lc];
                af[mt][1] = As[(r + 8) * PVP + kb + lc];
                af[mt][2] = As[r * PVP + kb + lc + 4];
                af[mt][3] = As[(r + 8) * PVP + kb + lc + 4];
            }
#pragma unroll
            for (int nt = 0; nt < 4; nt++) {
                int cN = wn + nt * 8 + lr;
                bf[nt][0] = Bs[cN * PVP + kb + lc];
                bf[nt][1] = Bs[cN * PVP + kb + lc + 4];
            }
#pragma unroll
            for (int mt = 0; mt < 4; mt++)
#pragma unroll
                for (int nt = 0; nt < 4; nt++)
                    mma_f16(acc[mt][nt], af[mt], bf[nt]);
        }
        __syncthreads();
        if (it + 2 < NIT)
            load_st((it + 2) * 32, sAu + s * 128 * PVP * 4, sBu + s * 128 * PVP * 4);
    }

    float* memb = memsegT + (size_t)bhs * DHEAD * DHEAD;
#pragma unroll
    for (int nt = 0; nt < 4; nt++) {
        int col = wn + nt * 8 + 2 * lc;
#pragma unroll
        for (int mt = 0; mt < 4; mt++) {
            int row = wm + mt * 16 + lr;
            *(float2*)&memb[(size_t)row * DHEAD + col] =
                make_float2(acc[mt][nt][0], acc[mt][nt][1]);
            *(float2*)&memb[(size_t)(row + 8) * DHEAD + col] =
                make_float2(acc[mt][nt][2], acc[mt][nt][3]);
        }
    }
}

// ============================================================================
// K7: in-place exclusive prefix over the 8 segments
// ============================================================================
__global__ __launch_bounds__(256) void prefix_mem_k(float* __restrict__ memseg)
{
    size_t idx = (size_t)blockIdx.x * 256 + threadIdx.x;
    int bh = (int)(idx >> 14);
    int off = (int)(idx & 16383);
    size_t base = ((size_t)bh * NSEG) * 16384 + off;
    float run = 0.f;
#pragma unroll
    for (int s = 0; s < NSEG; s++) {
        float t = memseg[base + (size_t)s * 16384];
        memseg[base + (size_t)s * 16384] = run;
        run += t;
    }
}

__global__ __launch_bounds__(256) void prefix_Z_k(float* __restrict__ Zseg)
{
    int idx = blockIdx.x * 256 + threadIdx.x;
    int bh = idx >> 7;
    int d = idx & 127;
    int base = bh * NSEG * DHEAD + d;
    float run = 0.f;
#pragma unroll
    for (int s = 0; s < NSEG; s++) {
        float t = Zseg[base + s * DHEAD];
        Zseg[base + s * DHEAD] = run;
        run += t;
    }
}

// ============================================================================
// Host launch
// ============================================================================
extern "C" void kernel_launch(void* const* d_in, const int* in_sizes, int n_in,
                              void* d_out, int out_size)
{
    (void)in_sizes; (void)n_in; (void)out_size;
    const float* x    = (const float*)d_in[0];
    const float* Wq   = (const float*)d_in[1];
    const float* bq   = (const float*)d_in[2];
    const float* Wk   = (const float*)d_in[3];
    const float* bk   = (const float*)d_in[4];
    const float* Wv   = (const float*)d_in[5];
    const float* bv   = (const float*)d_in[6];
    const float* Wo   = (const float*)d_in[7];
    const float* bo   = (const float*)d_in[8];
    const float* beta = (const float*)d_in[9];
    float* out = (float*)d_out;

    static float *pmemsegT = nullptr, *pZseg = nullptr, *pcost = nullptr, *psint = nullptr;
    static uint32_t *pWth = nullptr, *pxh = nullptr, *pattnh = nullptr,
                    *pqh = nullptr, *pkh = nullptr, *pvh = nullptr,
                    *pvth = nullptr, *pskth = nullptr;
    if (!pWth) {
        cudaGetSymbolAddress((void**)&pmemsegT, g_memsegT);
        cudaGetSymbolAddress((void**)&pZseg, g_Zseg);
        cudaGetSymbolAddress((void**)&pWth, g_Wth);
        cudaGetSymbolAddress((void**)&pxh, g_xh);
        cudaGetSymbolAddress((void**)&pattnh, g_attnh);
        cudaGetSymbolAddress((void**)&pqh, g_qh);
        cudaGetSymbolAddress((void**)&pkh, g_kh);
        cudaGetSymbolAddress((void**)&pvh, g_vh);
        cudaGetSymbolAddress((void**)&pvth, g_vth);
        cudaGetSymbolAddress((void**)&pskth, g_skth);
        cudaGetSymbolAddress((void**)&pcost, g_cost);
        cudaGetSymbolAddress((void**)&psint, g_sint);
        cudaFuncSetAttribute(gemm_mma_k, cudaFuncAttributeMaxDynamicSharedMemorySize,
                             GEMM_SMEM_BYTES);
        cudaFuncSetAttribute(gemm_qkv_k, cudaFuncAttributeMaxDynamicSharedMemorySize,
                             GEMM_SMEM_BYTES);
        cudaFuncSetAttribute(fam_k, cudaFuncAttributeMaxDynamicSharedMemorySize,
                             FAM_SMEM_BYTES);
        cudaFuncSetAttribute(outer_mma_k, cudaFuncAttributeMaxDynamicSharedMemorySize,
                             OUTER_SMEM_BYTES);
    }

    const size_t WSZ_U = (size_t)EMBD * EMBD_U;
    dim3 tblk(32, 8);
    transpose_fp16_all_k<<<dim3(EMBD / 32, EMBD / 32, 4), tblk>>>(Wq, Wk, Wv, Wo, pWth);

    perm_cvt_fp16_k<<<(int)(TOTAL / 16 / 256), 256>>>(x, pxh);
    rope_tab_k<<<(SEQ * 1024) / 256, 256>>>(pcost, psint);

    // QKV GEMM with fused rope + fp16 pack
    dim3 qkvgrid(EMBD / BN, MTOK / BM, 3);
    gemm_qkv_k<<<qkvgrid, 256, GEMM_SMEM_BYTES>>>(pxh, pWth, bq, bk, bv,
                                                  pqh, pkh, pvh, pcost, psint);

    // merged v^T / sk^T transposes
    vtskt_k<<<dim3(2, (SEGL / 32) * 2, NBH * NSEG), tblk>>>(pvh, pkh, pvth, pskth);

    // parallel linear-memory path (tensorized)
    outer_mma_k<<<NBH * NSEG, 256, OUTER_SMEM_BYTES>>>(pvth, pskth, pmemsegT);
    zsum_k<<<NBH * NSEG, 256>>>(pskth, pZseg);
    prefix_mem_k<<<(NBH * 16384) / 256, 256>>>(pmemsegT);
    prefix_Z_k<<<(NBH * DHEAD) / 256, 256>>>(pZseg);

    // fused flash attention + A_mem + combine, fp16-permuted output
    fam_k<<<dim3(SEGL / 128, NBH * NSEG), 256, FAM_SMEM_BYTES>>>(
        pqh, pkh, pvth, pmemsegT, pZseg, beta, pattnh);

    gemm_mma_k<<<dim3(EMBD / BN, MTOK / BM), 256, GEMM_SMEM_BYTES>>>(
        pattnh, pWth + 3 * WSZ_U, bo, out);
}

// round 16
// speedup vs baseline: 5.7800x; 1.0096x over previous
#include <cuda_runtime.h>
#include <cuda_fp16.h>
#include <math.h>
#include <stdint.h>

// Problem constants
#define SEQ   4096
#define EMBD  2048
#define NB    4
#define NHEAD 16
#define DHEAD 128
#define NSEG  8
#define SEGL  512
#define NBH   (NB * NHEAD)          // 64
#define MTOK  (NB * SEQ)            // 16384
#define TOTAL ((size_t)MTOK * EMBD) // 33554432
#define EMBD_U (EMBD / 2)           // 1024 u32 per row
#define SEGL_U (SEGL / 2)           // 256

// -------- device scratch ----------------------------------------------------
__device__ float g_memsegT[(size_t)NBH * NSEG * DHEAD * DHEAD]; // mem^T [e][d]
__device__ float g_Zseg[NBH * NSEG * DHEAD];
__device__ uint32_t g_Wth[(size_t)4 * EMBD * EMBD_U]; // transposed+permuted fp16
__device__ uint32_t g_xh[TOTAL / 2];                  // permuted fp16 x
__device__ uint32_t g_attnh[TOTAL / 2];               // permuted fp16 attn
__device__ uint32_t g_qh[TOTAL / 2];                  // fp16 q (pairs along d, roped)
__device__ uint32_t g_kh[TOTAL / 2];                  // fp16 k (pairs along d, roped)
__device__ uint32_t g_vh[TOTAL / 2];                  // fp16 v (pairs along d)
__device__ uint32_t g_vth[(size_t)NBH * NSEG * DHEAD * SEGL_U]; // fp16 v^T
__device__ uint32_t g_skth[(size_t)NBH * NSEG * DHEAD * SEGL_U]; // fp16 sk^T
__device__ float g_cost[(size_t)SEQ * 1024];          // rope cos table
__device__ float g_sint[(size_t)SEQ * 1024];          // rope sin table

__device__ __forceinline__ float elu1(float x) {
    return (x > 0.f) ? (x + 1.f) : expf(x);
}

__device__ __forceinline__ uint32_t smem_u32(const void* p) {
    uint32_t a;
    asm("{ .reg .u64 t; cvta.to.shared.u64 t, %1; cvt.u32.u64 %0, t; }"
        : "=r"(a) : "l"(p));
    return a;
}

__device__ __forceinline__ void cp16(uint32_t saddr, const void* g) {
    asm volatile("cp.async.cg.shared.global [%0], [%1], 16;" :: "r"(saddr), "l"(g));
}

__device__ __forceinline__ uint32_t f2tf32(float x) {
    uint32_t u;
    asm("cvt.rna.tf32.f32 %0, %1;" : "=r"(u) : "f"(x));
    return u;
}

__device__ __forceinline__ uint32_t packh2(float lo, float hi) {
    __half2 h = __floats2half2_rn(lo, hi);
    return *(uint32_t*)&h;
}

__device__ __forceinline__ void mma_tf32(float* d, const uint32_t* a, const uint32_t* b) {
    asm volatile(
        "mma.sync.aligned.m16n8k8.row.col.f32.tf32.tf32.f32 "
        "{%0,%1,%2,%3}, {%4,%5,%6,%7}, {%8,%9}, {%0,%1,%2,%3};"
        : "+f"(d[0]), "+f"(d[1]), "+f"(d[2]), "+f"(d[3])
        : "r"(a[0]), "r"(a[1]), "r"(a[2]), "r"(a[3]), "r"(b[0]), "r"(b[1]));
}

__device__ __forceinline__ void mma_f16(float* d, const uint32_t* a, const uint32_t* b) {
    asm volatile(
        "mma.sync.aligned.m16n8k16.row.col.f32.f16.f16.f32 "
        "{%0,%1,%2,%3}, {%4,%5,%6,%7}, {%8,%9}, {%0,%1,%2,%3};"
        : "+f"(d[0]), "+f"(d[1]), "+f"(d[2]), "+f"(d[3])
        : "r"(a[0]), "r"(a[1]), "r"(a[2]), "r"(a[3]), "r"(b[0]), "r"(b[1]));
}

__device__ __forceinline__ int pposu(int j) { return (j < 4) ? 2 * j : 2 * (j - 4) + 1; }

// ============================================================================
// K0a: transpose + u32-permute + fp16 convert of ALL 4 weights (blockIdx.z)
// ============================================================================
__global__ __launch_bounds__(256) void transpose_fp16_all_k(
    const float* __restrict__ Wq, const float* __restrict__ Wk,
    const float* __restrict__ Wv, const float* __restrict__ Wo,
    uint32_t* __restrict__ WthBase)
{
    __shared__ float t[32][33];
    int z = blockIdx.z;
    const float* W = (z == 0) ? Wq : (z == 1) ? Wk : (z == 2) ? Wv : Wo;
    uint32_t* Wth = WthBase + (size_t)z * EMBD * EMBD_U;
    int bx = blockIdx.x * 32, by = blockIdx.y * 32;
    int txx = threadIdx.x;
    for (int i = threadIdx.y; i < 32; i += 8)
        t[i][txx] = W[(size_t)(by + i) * EMBD + bx + txx];
    __syncthreads();
    if (txx < 16) {
        int j = txx & 7;
        int pos = (by >> 1) + (txx >> 3) * 8 + pposu(j);
        for (int i = threadIdx.y; i < 32; i += 8) {
            uint32_t u = packh2(t[2 * txx][i], t[2 * txx + 1][i]);
            Wth[(size_t)(bx + i) * EMBD_U + pos] = u;
        }
    }
}

// ============================================================================
// K0b: u32-permute + fp16 convert of x
// ============================================================================
__global__ __launch_bounds__(256) void perm_cvt_fp16_k(const float* __restrict__ src,
                                                       uint32_t* __restrict__ dst)
{
    size_t g16 = (size_t)blockIdx.x * 256 + threadIdx.x;
    size_t base = g16 * 16;
    float4 f0 = *(const float4*)&src[base];
    float4 f1 = *(const float4*)&src[base + 4];
    float4 f2 = *(const float4*)&src[base + 8];
    float4 f3 = *(const float4*)&src[base + 12];
    uint4 o0, o1;
    o0.x = packh2(f0.x, f0.y);
    o0.y = packh2(f2.x, f2.y);
    o0.z = packh2(f0.z, f0.w);
    o0.w = packh2(f2.z, f2.w);
    o1.x = packh2(f1.x, f1.y);
    o1.y = packh2(f3.x, f3.y);
    o1.z = packh2(f1.z, f1.w);
    o1.w = packh2(f3.z, f3.w);
    *(uint4*)&dst[g16 * 8] = o0;
    *(uint4*)&dst[g16 * 8 + 4] = o1;
}

// ============================================================================
// K0c: rope cos/sin tables
// ============================================================================
__global__ __launch_bounds__(256) void rope_tab_k(float* __restrict__ cost,
                                                  float* __restrict__ sint)
{
    size_t idx = (size_t)blockIdx.x * 256 + threadIdx.x;
    int t = (int)(idx >> 10);
    int i = (int)(idx & 1023);
    float inv = powf(10000.0f, -(float)(2 * i) * (1.0f / 2048.0f));
    float ang = (float)t * inv;
    cost[idx] = cosf(ang);
    sint[idx] = sinf(ang);
}

// ============================================================================
// K1: fp16 mma.sync GEMM mainloop — CUTLASS-style single-sync multistage
// ============================================================================
#define BM 128
#define BN 256
#define BK 32
#define BKU 16
#define BKP_U 24
#define NSTG 3
#define STG_U ((BM + BN) * BKP_U)
#define GEMM_SMEM_BYTES (NSTG * STG_U * 4)

__device__ __forceinline__ void load_stage_h(const uint32_t* __restrict__ A,
                                             const uint32_t* __restrict__ Bt,
                                             int brow, int bcol, int k0u,
                                             uint32_t sA, uint32_t sB, int tid)
{
#pragma unroll
    for (int it = 0; it < 2; it++) {
        int idx = tid + it * 256;
        int row = idx >> 2, c4 = idx & 3;
        cp16(sA + (row * BKP_U + c4 * 4) * 4,
             A + (size_t)(brow + row) * EMBD_U + k0u + c4 * 4);
    }
#pragma unroll
    for (int it = 0; it < 4; it++) {
        int idx = tid + it * 256;
        int row = idx >> 2, c4 = idx & 3;
        cp16(sB + (row * BKP_U + c4 * 4) * 4,
             Bt + (size_t)(bcol + row) * EMBD_U + k0u + c4 * 4);
    }
    asm volatile("cp.async.commit_group;" ::: "memory");
}

__device__ __forceinline__ void gemm_mainloop(
    const uint32_t* __restrict__ A, const uint32_t* __restrict__ Bt,
    uint32_t* dsm_u, float acc[4][8][4], int brow, int bcol,
    int tid, int wm, int wn, int lr, int lc)
{
    uint32_t sbase = smem_u32(dsm_u);
    uint32_t sA[NSTG], sB[NSTG];
#pragma unroll
    for (int s = 0; s < NSTG; s++) {
        sA[s] = sbase + s * STG_U * 4;
        sB[s] = sA[s] + BM * BKP_U * 4;
    }

    // prologue: commit only 2 stages (single-sync multistage)
    load_stage_h(A, Bt, brow, bcol, 0 * BKU, sA[0], sB[0], tid);
    load_stage_h(A, Bt, brow, bcol, 1 * BKU, sA[1], sB[1], tid);

    const int NIT = EMBD / BK;
    for (int it = 0; it < NIT; it++) {
        if (it < NIT - 1) asm volatile("cp.async.wait_group 1;" ::: "memory");
        else              asm volatile("cp.async.wait_group 0;" ::: "memory");
        __syncthreads();

        // issue next-next stage load BEFORE compute (overlaps with MMA)
        if (it + 2 < NIT) {
            int sn = (it + 2) % NSTG;
            load_stage_h(A, Bt, brow, bcol, (it + 2) * BKU, sA[sn], sB[sn], tid);
        }

        int s = it % NSTG;
        const uint32_t* As = dsm_u + (size_t)s * STG_U;
        const uint32_t* Bs = As + BM * BKP_U;

#pragma unroll
        for (int kc = 0; kc < 2; kc++) {
            int off = kc * 8 + 2 * lc;
            uint32_t af[4][4], bf[8][2];
#pragma unroll
            for (int mt = 0; mt < 4; mt++) {
                int r = wm + mt * 16 + lr;
                uint2 a0 = *(const uint2*)&As[r * BKP_U + off];
                uint2 a1 = *(const uint2*)&As[(r + 8) * BKP_U + off];
                af[mt][0] = a0.x; af[mt][2] = a0.y;
                af[mt][1] = a1.x; af[mt][3] = a1.y;
            }
#pragma unroll
            for (int nt = 0; nt < 8; nt++) {
                int cN = wn + nt * 8 + lr;
                uint2 b = *(const uint2*)&Bs[cN * BKP_U + off];
                bf[nt][0] = b.x; bf[nt][1] = b.y;
            }
#pragma unroll
            for (int mt = 0; mt < 4; mt++)
#pragma unroll
                for (int nt = 0; nt < 8; nt++)
                    mma_f16(acc[mt][nt], af[mt], bf[nt]);
        }
        // no trailing sync: next iteration's top barrier covers the hazard
    }
}

// final GEMM: fp32 output + bias
__global__ __launch_bounds__(256) void gemm_mma_k(
    const uint32_t* __restrict__ A, const uint32_t* __restrict__ Bt,
    const float* __restrict__ bias, float* __restrict__ C)
{
    extern __shared__ uint32_t dsm_u[];
    const int tid = threadIdx.x;
    const int wid = tid >> 5;
    const int lane = tid & 31;
    const int lr = lane >> 2, lc = lane & 3;
    const int wm = (wid >> 2) * 64, wn = (wid & 3) * 64;
    int brow = blockIdx.y * BM, bcol = blockIdx.x * BN;

    float acc[4][8][4];
#pragma unroll
    for (int mt = 0; mt < 4; mt++)
#pragma unroll
        for (int nt = 0; nt < 8; nt++)
#pragma unroll
            for (int r = 0; r < 4; r++) acc[mt][nt][r] = 0.f;

    gemm_mainloop(A, Bt, dsm_u, acc, brow, bcol, tid, wm, wn, lr, lc);

#pragma unroll
    for (int nt = 0; nt < 8; nt++) {
        int col = bcol + wn + nt * 8 + 2 * lc;
        float b0 = bias[col], b1 = bias[col + 1];
#pragma unroll
        for (int mt = 0; mt < 4; mt++) {
            int row = brow + wm + mt * 16 + lr;
            float2 v0 = make_float2(acc[mt][nt][0] + b0, acc[mt][nt][1] + b1);
            float2 v1 = make_float2(acc[mt][nt][2] + b0, acc[mt][nt][3] + b1);
            *(float2*)&C[(size_t)row * EMBD + col] = v0;
            *(float2*)&C[(size_t)(row + 8) * EMBD + col] = v1;
        }
    }
}

// QKV GEMM: fused bias + rope (z<2) + fp16 pack
__global__ __launch_bounds__(256) void gemm_qkv_k(
    const uint32_t* __restrict__ A, const uint32_t* __restrict__ WtBase,
    const float* __restrict__ bq, const float* __restrict__ bk,
    const float* __restrict__ bv,
    uint32_t* __restrict__ qh, uint32_t* __restrict__ kh, uint32_t* __restrict__ vh,
    const float* __restrict__ cost, const float* __restrict__ sint)
{
    extern __shared__ uint32_t dsm_u[];
    const int tid = threadIdx.x;
    const int wid = tid >> 5;
    const int lane = tid & 31;
    const int lr = lane >> 2, lc = lane & 3;
    const int wm = (wid >> 2) * 64, wn = (wid & 3) * 64;
    int brow = blockIdx.y * BM, bcol = blockIdx.x * BN;

    int z = blockIdx.z;
    const uint32_t* Bt = WtBase + (size_t)z * EMBD * EMBD_U;
    const float* bias = (z == 0) ? bq : (z == 1) ? bk : bv;
    uint32_t* Ch = (z == 0) ? qh : (z == 1) ? kh : vh;
    bool dorope = (z < 2);

    float acc[4][8][4];
#pragma unroll
    for (int mt = 0; mt < 4; mt++)
#pragma unroll
        for (int nt = 0; nt < 8; nt++)
#pragma unroll
            for (int r = 0; r < 4; r++) acc[mt][nt][r] = 0.f;

    gemm_mainloop(A, Bt, dsm_u, acc, brow, bcol, tid, wm, wn, lr, lc);

#pragma unroll
    for (int nt = 0; nt < 8; nt++) {
        int col = bcol + wn + nt * 8 + 2 * lc;
        int pi = col >> 1;
        float b0 = bias[col], b1 = bias[col + 1];
#pragma unroll
        for (int mt = 0; mt < 4; mt++) {
#pragma unroll
            for (int h = 0; h < 2; h++) {
                int row = brow + wm + mt * 16 + lr + h * 8;
                float a0 = acc[mt][nt][2 * h + 0] + b0;
                float a1 = acc[mt][nt][2 * h + 1] + b1;
                if (dorope) {
                    int t = row & (SEQ - 1);
                    float c = cost[(size_t)t * 1024 + pi];
                    float s = sint[(size_t)t * 1024 + pi];
                    float r0 = a0 * c - a1 * s;
                    float r1 = a0 * s + a1 * c;
                    a0 = r0; a1 = r1;
                }
                Ch[(size_t)row * EMBD_U + pi] = packh2(a0, a1);
            }
        }
    }
}

// ============================================================================
// K2b: merged v^T / sk^T transposes (blockIdx.y parity selects path)
// ============================================================================
__global__ __launch_bounds__(256) void vtskt_k(const uint32_t* __restrict__ vh,
                                               const uint32_t* __restrict__ kh,
                                               uint32_t* __restrict__ vth,
                                               uint32_t* __restrict__ skth)
{
    __shared__ float t[32][68];
    int bhs = blockIdx.z;
    int p0 = blockIdx.x * 32;
    int which = blockIdx.y & 1;               // 0 = v, 1 = sk
    int l0 = (blockIdx.y >> 1) * 32;
    const uint32_t* seg = (which ? kh : vh) + ((size_t)bhs << 15);
    uint32_t* dst = (which ? skth : vth) + (size_t)bhs * DHEAD * SEGL_U;
    int txx = threadIdx.x, ty = threadIdx.y;
    for (int i = ty; i < 32; i += 8) {
        __half2 h = *(const __half2*)&seg[(size_t)(l0 + i) * 64 + p0 + txx];
        t[i][2 * txx] = __low2float(h);
        t[i][2 * txx + 1] = __high2float(h);
    }
    __syncthreads();
    int tid = ty * 32 + txx;
#pragma unroll
    for (int j = 0; j < 4; j++) {
        int flat = tid + j * 256;
        int d = flat >> 4, c = flat & 15;
        float a = t[2 * c][d], b = t[2 * c + 1][d];
        if (which) { a = elu1(a); b = elu1(b); }
        dst[(size_t)(2 * p0 + d) * SEGL_U + (l0 >> 1) + c] = packh2(a, b);
    }
}

// ============================================================================
// K2d: Zseg[bhs][d] = row-sum of skth
// ============================================================================
__global__ __launch_bounds__(256) void zsum_k(const uint32_t* __restrict__ skth,
                                              float* __restrict__ Zseg)
{
    int bhs = blockIdx.x;
    int tid = threadIdx.x;
    int d = tid >> 1;
    int half = tid & 1;
    const uint32_t* row = skth + (size_t)bhs * DHEAD * SEGL_U
                        + (size_t)d * SEGL_U + half * 128;
    float s = 0.f;
#pragma unroll 16
    for (int j = 0; j < 128; j++) {
        __half2 h = *(const __half2*)&row[j];
        s += __low2float(h) + __high2float(h);
    }
    s += __shfl_xor_sync(0xffffffffu, s, 1);
    if (half == 0) Zseg[bhs * DHEAD + d] = s;
}

// ============================================================================
// K3: FUSED flash attention + A_mem + combine, with pipelined k/v prefetch
// ============================================================================
#define SCP 68
#define AMP 136
#define FAM_U32 (43520 + 1536)
#define FAM_SMEM_BYTES (FAM_U32 * 4)   // 180224

__global__ __launch_bounds__(256, 1) void fam_k(
    const uint32_t* __restrict__ qh, const uint32_t* __restrict__ kh,
    const uint32_t* __restrict__ vth, const float* __restrict__ memsegT,
    const float* __restrict__ Zseg, const float* __restrict__ beta,
    uint32_t* __restrict__ attnh)
{
    extern __shared__ uint32_t smu[];
    uint32_t* qs = smu;
    uint32_t* ks = smu + 128 * SCP;
    uint32_t* Ps = smu + 2 * 128 * SCP;
    uint32_t* vsb[2] = { smu + 3 * 128 * SCP, smu + 4 * 128 * SCP };
    uint32_t* aq = smu + 128 * SCP;
    uint32_t* ms = smu + 3 * 128 * SCP;
    float* pmax = (float*)(smu + 43520);
    float* psum = pmax + 4 * 128;
    float* m_s = psum + 4 * 128;
    float* f_s = m_s + 128;
    float* ssum_s = f_s + 128;
    float* Zs = ssum_s + 128;

    uint32_t sq = smem_u32(qs);
    uint32_t sk = smem_u32(ks);
    uint32_t sv0 = smem_u32(vsb[0]);
    uint32_t sv1 = smem_u32(vsb[1]);
    uint32_t smb = smem_u32(ms);

    const float scale = 0.08838834764831845f;
    const int tid = threadIdx.x;
    const int wid = tid >> 5;
    const int lane = tid & 31;
    const int lr = lane >> 2;
    const int lc = lane & 3;
    const int wm = (wid >> 2) * 64;
    const int wn = (wid & 3) * 32;
    const int wci = wid & 3;

    int bhs = blockIdx.y;
    int l0 = blockIdx.x * 128;
    size_t segbase_u = ((size_t)bhs) << 15;
    const uint32_t* qseg = qh + segbase_u;
    const uint32_t* kseg = kh + segbase_u;
    const uint32_t* vtseg = vth + (size_t)bhs * DHEAD * SEGL_U;
    const float* memb = memsegT + (size_t)bhs * DHEAD * DHEAD;
    float g = 1.0f / (1.0f + expf(-beta[0]));
    float gm1 = 1.0f - g;

#pragma unroll
    for (int it = 0; it < 8; it++) {
        int idx = tid + it * 256;
        int row = idx >> 4, c4 = idx & 15;
        cp16(sq + (row * SCP + c4 * 4) * 4,
             qseg + (size_t)(l0 + row) * 64 + c4 * 4);
    }
#pragma unroll
    for (int it = 0; it < 8; it++) {
        int idx = tid + it * 256;
        int row = idx >> 4, c4 = idx & 15;
        cp16(sk + (row * SCP + c4 * 4) * 4,
             kseg + (size_t)row * 64 + c4 * 4);
    }
#pragma unroll
    for (int it = 0; it < 8; it++) {
        int idx = tid + it * 256;
        int row = idx >> 4, c4 = idx & 15;
        cp16(sv0 + (row * SCP + c4 * 4) * 4,
             vtseg + (size_t)row * SEGL_U + c4 * 4);
    }
    asm volatile("cp.async.commit_group;" ::: "memory");

    if (tid < 128) { m_s[tid] = -1e30f; ssum_s[tid] = 0.f; }

    float Oacc[4][4][4];
#pragma unroll
    for (int mt = 0; mt < 4; mt++)
#pragma unroll
        for (int nt = 0; nt < 4; nt++)
#pragma unroll
            for (int r = 0; r < 4; r++) Oacc[mt][nt][r] = 0.f;

    for (int kt = 0; kt < 4; kt++) {
        uint32_t* vs = vsb[kt & 1];
        asm volatile("cp.async.wait_group 0;" ::: "memory");
        __syncthreads();

        float Sacc[4][4][4];
#pragma unroll
        for (int mt = 0; mt < 4; mt++)
#pragma unroll
            for (int nt = 0; nt < 4; nt++)
#pragma unroll
                for (int r = 0; r < 4; r++) Sacc[mt][nt][r] = 0.f;

#pragma unroll
        for (int kb = 0; kb < 64; kb += 8) {
            uint32_t af[4][4], bf[4][2];
#pragma unroll
            for (int mt = 0; mt < 4; mt++) {
                int r = wm + mt * 16 + lr;
                af[mt][0] = qs[r * SCP + kb + lc];
                af[mt][1] = qs[(r + 8) * SCP + kb + lc];
                af[mt][2] = qs[r * SCP + kb + lc + 4];
                af[mt][3] = qs[(r + 8) * SCP + kb + lc + 4];
            }
#pragma unroll
            for (int nt = 0; nt < 4; nt++) {
                int cN = wn + nt * 8 + lr;
                bf[nt][0] = ks[cN * SCP + kb + lc];
                bf[nt][1] = ks[cN * SCP + kb + lc + 4];
            }
#pragma unroll
            for (int mt = 0; mt < 4; mt++)
#pragma unroll
                for (int nt = 0; nt < 4; nt++)
                    mma_f16(Sacc[mt][nt], af[mt], bf[nt]);
        }
#pragma unroll
        for (int mt = 0; mt < 4; mt++)
#pragma unroll
            for (int nt = 0; nt < 4; nt++)
#pragma unroll
                for (int r = 0; r < 4; r++) Sacc[mt][nt][r] *= scale;

#pragma unroll
        for (int mt = 0; mt < 4; mt++) {
#pragma unroll
            for (int h = 0; h < 2; h++) {
                float mv = -1e30f;
#pragma unroll
                for (int nt = 0; nt < 4; nt++) {
                    mv = fmaxf(mv, Sacc[mt][nt][2 * h]);
                    mv = fmaxf(mv, Sacc[mt][nt][2 * h + 1]);
                }
                mv = fmaxf(mv, __shfl_xor_sync(0xffffffffu, mv, 1));
                mv = fmaxf(mv, __shfl_xor_sync(0xffffffffu, mv, 2));
                if (lc == 0) pmax[wci * 128 + wm + mt * 16 + lr + h * 8] = mv;
            }
        }
        __syncthreads();
        if (kt < 3) {
            uint32_t svn = (kt & 1) ? sv0 : sv1;
#pragma unroll
            for (int it = 0; it < 8; it++) {
                int idx = tid + it * 256;
                int row = idx >> 4, c4 = idx & 15;
                cp16(sk + (row * SCP + c4 * 4) * 4,
                     kseg + (size_t)((kt + 1) * 128 + row) * 64 + c4 * 4);
            }
#pragma unroll
            for (int it = 0; it < 8; it++) {
                int idx = tid + it * 256;
                int row = idx >> 4, c4 = idx & 15;
                cp16(svn + (row * SCP + c4 * 4) * 4,
                     vtseg + (size_t)row * SEGL_U + (kt + 1) * 64 + c4 * 4);
            }
            asm volatile("cp.async.commit_group;" ::: "memory");
        }

        if (tid < 128) {
            float mo = m_s[tid];
            float nm = fmaxf(fmaxf(pmax[tid], pmax[128 + tid]),
                             fmaxf(pmax[256 + tid], pmax[384 + tid]));
            float mn = fmaxf(mo, nm);
            float f = expf(mo - mn);
            m_s[tid] = mn;
            f_s[tid] = f;
            ssum_s[tid] *= f;
        }
        __syncthreads();

#pragma unroll
        for (int mt = 0; mt < 4; mt++) {
#pragma unroll
            for (int h = 0; h < 2; h++) {
                int row = wm + mt * 16 + lr + h * 8;
                float m = m_s[row];
                float f = f_s[row];
                float rsum = 0.f;
#pragma unroll
                for (int nt = 0; nt < 4; nt++) {
                    float p0 = expf(Sacc[mt][nt][2 * h] - m);
                    float p1 = expf(Sacc[mt][nt][2 * h + 1] - m);
                    rsum += p0 + p1;
                    Ps[row * SCP + (wn >> 1) + nt * 4 + lc] = packh2(p0, p1);
                    Oacc[mt][nt][2 * h] *= f;
                    Oacc[mt][nt][2 * h + 1] *= f;
                }
                rsum += __shfl_xor_sync(0xffffffffu, rsum, 1);
                rsum += __shfl_xor_sync(0xffffffffu, rsum, 2);
                if (lc == 0) psum[wci * 128 + row] = rsum;
            }
        }
        __syncthreads();

        if (tid < 128)
            ssum_s[tid] += psum[tid] + psum[128 + tid] + psum[256 + tid] + psum[384 + tid];

#pragma unroll
        for (int kb = 0; kb < 64; kb += 8) {
            uint32_t af[4][4], bf[4][2];
#pragma unroll
            for (int mt = 0; mt < 4; mt++) {
                int r = wm + mt * 16 + lr;
                af[mt][0] = Ps[r * SCP + kb + lc];
                af[mt][1] = Ps[(r + 8) * SCP + kb + lc];
                af[mt][2] = Ps[r * SCP + kb + lc + 4];
                af[mt][3] = Ps[(r + 8) * SCP + kb + lc + 4];
            }
#pragma unroll
            for (int nt = 0; nt < 4; nt++) {
                int cN = wn + nt * 8 + lr;
                bf[nt][0] = vs[cN * SCP + kb + lc];
                bf[nt][1] = vs[cN * SCP + kb + lc + 4];
            }
#pragma unroll
            for (int mt = 0; mt < 4; mt++)
#pragma unroll
                for (int nt = 0; nt < 4; nt++)
                    mma_f16(Oacc[mt][nt], af[mt], bf[nt]);
        }
        __syncthreads();
    }

    // ---------------- amem phase ----------------
#pragma unroll
    for (int it = 0; it < 16; it++) {
        int idx = tid + it * 256;
        int row = idx >> 5, c4 = idx & 31;
        cp16(smb + (row * AMP + c4 * 4) * 4,
             memb + (size_t)row * DHEAD + c4 * 4);
    }
    asm volatile("cp.async.commit_group;" ::: "memory");

#pragma unroll
    for (int it = 0; it < 32; it++) {
        int flat = it * 256 + tid;
        int row = flat >> 6, col = flat & 63;
        __half2 h = *(const __half2*)&qs[row * SCP + col];
        aq[row * AMP + 2 * col]     = f2tf32(elu1(__low2float(h)));
        aq[row * AMP + 2 * col + 1] = f2tf32(elu1(__high2float(h)));
    }
    asm volatile("cp.async.wait_group 0;" ::: "memory");
    __syncthreads();

    {
        int r = tid >> 1;
        int half = (tid & 1) * 64;
        float partial = 0.f;
#pragma unroll 16
        for (int j = 0; j < 64; j++)
            partial += __uint_as_float(aq[r * AMP + half + j]);
        partial += __shfl_xor_sync(0xffffffffu, partial, 1);
        if ((tid & 1) == 0) pmax[r] = partial;
#pragma unroll 16
        for (int j = 0; j < 64; j++) {
            uint32_t* p = &ms[r * AMP + half + j];
            *p = f2tf32(__uint_as_float(*p));
        }
    }
    if (tid < 128) Zs[tid] = Zseg[bhs * DHEAD + tid];
    __syncthreads();

    float acc[4][4][4];
#pragma unroll
    for (int mt = 0; mt < 4; mt++)
#pragma unroll
        for (int nt = 0; nt < 4; nt++)
#pragma unroll
            for (int r = 0; r < 4; r++) acc[mt][nt][r] = 0.f;

#pragma unroll
    for (int kb = 0; kb < 128; kb += 8) {
        uint32_t af[4][4], bf[4][2];
#pragma unroll
        for (int mt = 0; mt < 4; mt++) {
            int r = wm + mt * 16 + lr;
            af[mt][0] = aq[r * AMP + kb + lc];
            af[mt][1] = aq[(r + 8) * AMP + kb + lc];
            af[mt][2] = aq[r * AMP + kb + lc + 4];
            af[mt][3] = aq[(r + 8) * AMP + kb + lc + 4];
        }
#pragma unroll
        for (int nt = 0; nt < 4; nt++) {
            int cN = wn + nt * 8 + lr;
            bf[nt][0] = ms[cN * AMP + kb + lc];
            bf[nt][1] = ms[cN * AMP + kb + lc + 4];
        }
#pragma unroll
        for (int mt = 0; mt < 4; mt++)
#pragma unroll
            for (int nt = 0; nt < 4; nt++)
                mma_tf32(acc[mt][nt], af[mt], bf[nt]);
    }

#pragma unroll
    for (int nt = 0; nt < 4; nt++) {
        int col = wn + nt * 8 + 2 * lc;
        int j = (col & 15) >> 1;
        int pos = (col >> 4) * 8 + pposu(j);
        float Z0 = Zs[col], Z1 = Zs[col + 1];
#pragma unroll
        for (int mt = 0; mt < 4; mt++) {
#pragma unroll
            for (int h = 0; h < 2; h++) {
                int rloc = wm + mt * 16 + lr + h * 8;
                int row = l0 + rloc;
                float rs = pmax[rloc];
                float sc = gm1 / ssum_s[rloc];
                float a0 = g * acc[mt][nt][2 * h + 0] / (rs * Z0 + 1e-6f)
                         + Oacc[mt][nt][2 * h + 0] * sc;
                float a1 = g * acc[mt][nt][2 * h + 1] / (rs * Z1 + 1e-6f)
                         + Oacc[mt][nt][2 * h + 1] * sc;
                attnh[segbase_u + (size_t)row * (DHEAD / 2) + pos] = packh2(a0, a1);
            }
        }
    }
}

// ============================================================================
// K6: tensorized outer products: memT[e][d] = sum_l v[l][e] * sk[l][d]
// ============================================================================
#define PVP 36
#define OUTER_SMEM_BYTES (2 * 2 * 128 * PVP * 4)

__global__ __launch_bounds__(256) void outer_mma_k(
    const uint32_t* __restrict__ vth, const uint32_t* __restrict__ skth,
    float* __restrict__ memsegT)
{
    extern __shared__ uint32_t smu[];
    uint32_t* Ash = smu;
    uint32_t* Bsh = smu + 2 * 128 * PVP;
    uint32_t sAu = smem_u32(Ash);
    uint32_t sBu = smem_u32(Bsh);

    const int tid = threadIdx.x;
    const int wid = tid >> 5;
    const int lane = tid & 31;
    const int lr = lane >> 2;
    const int lc = lane & 3;
    const int wm = (wid >> 2) * 64;
    const int wn = (wid & 3) * 32;

    int bhs = blockIdx.x;
    const uint32_t* vtseg = vth + (size_t)bhs * DHEAD * SEGL_U;
    const uint32_t* sktseg = skth + (size_t)bhs * DHEAD * SEGL_U;

    float acc[4][4][4];
#pragma unroll
    for (int mt = 0; mt < 4; mt++)
#pragma unroll
        for (int nt = 0; nt < 4; nt++)
#pragma unroll
            for (int r = 0; r < 4; r++) acc[mt][nt][r] = 0.f;

    auto load_st = [&](int k0u, uint32_t sA, uint32_t sB) {
#pragma unroll
        for (int it = 0; it < 4; it++) {
            int idx = tid + it * 256;
            int row = idx >> 3, c4 = idx & 7;
            cp16(sA + (row * PVP + c4 * 4) * 4,
                 vtseg + (size_t)row * SEGL_U + k0u + c4 * 4);
        }
#pragma unroll
        for (int it = 0; it < 4; it++) {
            int idx = tid + it * 256;
            int row = idx >> 3, c4 = idx & 7;
            cp16(sB + (row * PVP + c4 * 4) * 4,
                 sktseg + (size_t)row * SEGL_U + k0u + c4 * 4);
        }
        asm volatile("cp.async.commit_group;" ::: "memory");
    };

    load_st(0, sAu, sBu);
    load_st(32, sAu + 128 * PVP * 4, sBu + 128 * PVP * 4);

    const int NIT = SEGL_U / 32;
    for (int it = 0; it < NIT; it++) {
        int s = it & 1;
        if (it == NIT - 1) asm volatile("cp.async.wait_group 0;" ::: "memory");
        else               asm volatile("cp.async.wait_group 1;" ::: "memory");
        __syncthreads();

        const uint32_t* As = Ash + s * 128 * PVP;
        const uint32_t* Bs = Bsh + s * 128 * PVP;
#pragma unroll
        for (int kb = 0; kb < 32; kb += 8) {
            uint32_t af[4][4], bf[4][2];
#pragma unroll
            for (int mt = 0; mt < 4; mt++) {
                int r = wm + mt * 16 + lr;
                af[mt][0] = As[r * PVP + kb + lc];
                af[mt][1] = As[(r + 8) * PVP + kb + lc];
                af[mt][2] = As[r * PVP + kb + lc + 4];
                af[mt][3] = As[(r + 8) * PVP + kb + lc + 4];
            }
#pragma unroll
            for (int nt = 0; nt < 4; nt++) {
                int cN = wn + nt * 8 + lr;
                bf[nt][0] = Bs[cN * PVP + kb + lc];
                bf[nt][1] = Bs[cN * PVP + kb + lc + 4];
            }
#pragma unroll
            for (int mt = 0; mt < 4; mt++)
#pragma unroll
                for (int nt = 0; nt < 4; nt++)
                    mma_f16(acc[mt][nt], af[mt], bf[nt]);
        }
        __syncthreads();
        if (it + 2 < NIT)
            load_st((it + 2) * 32, sAu + s * 128 * PVP * 4, sBu + s * 128 * PVP * 4);
    }

    float* memb = memsegT + (size_t)bhs * DHEAD * DHEAD;
#pragma unroll
    for (int nt = 0; nt < 4; nt++) {
        int col = wn + nt * 8 + 2 * lc;
#pragma unroll
        for (int mt = 0; mt < 4; mt++) {
            int row = wm + mt * 16 + lr;
            *(float2*)&memb[(size_t)row * DHEAD + col] =
                make_float2(acc[mt][nt][0], acc[mt][nt][1]);
            *(float2*)&memb[(size_t)(row + 8) * DHEAD + col] =
                make_float2(acc[mt][nt][2], acc[mt][nt][3]);
        }
    }
}

// ============================================================================
// K7: in-place exclusive prefix over the 8 segments
// ============================================================================
__global__ __launch_bounds__(256) void prefix_mem_k(float* __restrict__ memseg)
{
    size_t idx = (size_t)blockIdx.x * 256 + threadIdx.x;
    int bh = (int)(idx >> 14);
    int off = (int)(idx & 16383);
    size_t base = ((size_t)bh * NSEG) * 16384 + off;
    float run = 0.f;
#pragma unroll
    for (int s = 0; s < NSEG; s++) {
        float t = memseg[base + (size_t)s * 16384];
        memseg[base + (size_t)s * 16384] = run;
        run += t;
    }
}

__global__ __launch_bounds__(256) void prefix_Z_k(float* __restrict__ Zseg)
{
    int idx = blockIdx.x * 256 + threadIdx.x;
    int bh = idx >> 7;
    int d = idx & 127;
    int base = bh * NSEG * DHEAD + d;
    float run = 0.f;
#pragma unroll
    for (int s = 0; s < NSEG; s++) {
        float t = Zseg[base + s * DHEAD];
        Zseg[base + s * DHEAD] = run;
        run += t;
    }
}

// ============================================================================
// Host launch
// ============================================================================
extern "C" void kernel_launch(void* const* d_in, const int* in_sizes, int n_in,
                              void* d_out, int out_size)
{
    (void)in_sizes; (void)n_in; (void)out_size;
    const float* x    = (const float*)d_in[0];
    const float* Wq   = (const float*)d_in[1];
    const float* bq   = (const float*)d_in[2];
    const float* Wk   = (const float*)d_in[3];
    const float* bk   = (const float*)d_in[4];
    const float* Wv   = (const float*)d_in[5];
    const float* bv   = (const float*)d_in[6];
    const float* Wo   = (const float*)d_in[7];
    const float* bo   = (const float*)d_in[8];
    const float* beta = (const float*)d_in[9];
    float* out = (float*)d_out;

    static float *pmemsegT = nullptr, *pZseg = nullptr, *pcost = nullptr, *psint = nullptr;
    static uint32_t *pWth = nullptr, *pxh = nullptr, *pattnh = nullptr,
                    *pqh = nullptr, *pkh = nullptr, *pvh = nullptr,
                    *pvth = nullptr, *pskth = nullptr;
    if (!pWth) {
        cudaGetSymbolAddress((void**)&pmemsegT, g_memsegT);
        cudaGetSymbolAddress((void**)&pZseg, g_Zseg);
        cudaGetSymbolAddress((void**)&pWth, g_Wth);
        cudaGetSymbolAddress((void**)&pxh, g_xh);
        cudaGetSymbolAddress((void**)&pattnh, g_attnh);
        cudaGetSymbolAddress((void**)&pqh, g_qh);
        cudaGetSymbolAddress((void**)&pkh, g_kh);
        cudaGetSymbolAddress((void**)&pvh, g_vh);
        cudaGetSymbolAddress((void**)&pvth, g_vth);
        cudaGetSymbolAddress((void**)&pskth, g_skth);
        cudaGetSymbolAddress((void**)&pcost, g_cost);
        cudaGetSymbolAddress((void**)&psint, g_sint);
        cudaFuncSetAttribute(gemm_mma_k, cudaFuncAttributeMaxDynamicSharedMemorySize,
                             GEMM_SMEM_BYTES);
        cudaFuncSetAttribute(gemm_qkv_k, cudaFuncAttributeMaxDynamicSharedMemorySize,
                             GEMM_SMEM_BYTES);
        cudaFuncSetAttribute(fam_k, cudaFuncAttributeMaxDynamicSharedMemorySize,
                             FAM_SMEM_BYTES);
        cudaFuncSetAttribute(outer_mma_k, cudaFuncAttributeMaxDynamicSharedMemorySize,
                             OUTER_SMEM_BYTES);
    }

    const size_t WSZ_U = (size_t)EMBD * EMBD_U;
    dim3 tblk(32, 8);
    transpose_fp16_all_k<<<dim3(EMBD / 32, EMBD / 32, 4), tblk>>>(Wq, Wk, Wv, Wo, pWth);

    perm_cvt_fp16_k<<<(int)(TOTAL / 16 / 256), 256>>>(x, pxh);
    rope_tab_k<<<(SEQ * 1024) / 256, 256>>>(pcost, psint);

    // QKV GEMM with fused rope + fp16 pack
    dim3 qkvgrid(EMBD / BN, MTOK / BM, 3);
    gemm_qkv_k<<<qkvgrid, 256, GEMM_SMEM_BYTES>>>(pxh, pWth, bq, bk, bv,
                                                  pqh, pkh, pvh, pcost, psint);

    // merged v^T / sk^T transposes
    vtskt_k<<<dim3(2, (SEGL / 32) * 2, NBH * NSEG), tblk>>>(pvh, pkh, pvth, pskth);

    // parallel linear-memory path (tensorized)
    outer_mma_k<<<NBH * NSEG, 256, OUTER_SMEM_BYTES>>>(pvth, pskth, pmemsegT);
    zsum_k<<<NBH * NSEG, 256>>>(pskth, pZseg);
    prefix_mem_k<<<(NBH * 16384) / 256, 256>>>(pmemsegT);
    prefix_Z_k<<<(NBH * DHEAD) / 256, 256>>>(pZseg);

    // fused flash attention + A_mem + combine, fp16-permuted output
    fam_k<<<dim3(SEGL / 128, NBH * NSEG), 256, FAM_SMEM_BYTES>>>(
        pqh, pkh, pvth, pmemsegT, pZseg, beta, pattnh);

    gemm_mma_k<<<dim3(EMBD / BN, MTOK / BM), 256, GEMM_SMEM_BYTES>>>(
        pattnh, pWth + 3 * WSZ_U, bo, out);
}

// round 17
// speedup vs baseline: 6.3174x; 1.0930x over previous
#include <cuda_runtime.h>
#include <cuda_fp16.h>
#include <math.h>
#include <stdint.h>

// Problem constants
#define SEQ   4096
#define EMBD  2048
#define NB    4
#define NHEAD 16
#define DHEAD 128
#define NSEG  8
#define SEGL  512
#define NBH   (NB * NHEAD)          // 64
#define MTOK  (NB * SEQ)            // 16384
#define TOTAL ((size_t)MTOK * EMBD) // 33554432
#define EMBD_U (EMBD / 2)           // 1024 u32 per row
#define SEGL_U (SEGL / 2)           // 256

// -------- device scratch ----------------------------------------------------
__device__ float g_memsegT[(size_t)NBH * NSEG * DHEAD * DHEAD]; // mem^T [e][d]
__device__ float g_Zseg[NBH * NSEG * DHEAD];
__device__ uint32_t g_Wth[(size_t)4 * EMBD * EMBD_U]; // transposed+permuted fp16
__device__ uint32_t g_xh[TOTAL / 2];                  // permuted fp16 x
__device__ uint32_t g_attnh[TOTAL / 2];               // permuted fp16 attn
__device__ uint32_t g_qh[TOTAL / 2];                  // fp16 q (pairs along d, roped)
__device__ uint32_t g_kh[TOTAL / 2];                  // fp16 k (pairs along d, roped)
__device__ uint32_t g_vh[TOTAL / 2];                  // fp16 v (pairs along d)
__device__ uint32_t g_vth[(size_t)NBH * NSEG * DHEAD * SEGL_U]; // fp16 v^T
__device__ uint32_t g_skth[(size_t)NBH * NSEG * DHEAD * SEGL_U]; // fp16 sk^T
__device__ float g_cost[(size_t)SEQ * 1024];          // rope cos table
__device__ float g_sint[(size_t)SEQ * 1024];          // rope sin table

__device__ __forceinline__ float elu1(float x) {
    return (x > 0.f) ? (x + 1.f) : expf(x);
}

__device__ __forceinline__ uint32_t smem_u32(const void* p) {
    uint32_t a;
    asm("{ .reg .u64 t; cvta.to.shared.u64 t, %1; cvt.u32.u64 %0, t; }"
        : "=r"(a) : "l"(p));
    return a;
}

__device__ __forceinline__ void cp16(uint32_t saddr, const void* g) {
    asm volatile("cp.async.cg.shared.global [%0], [%1], 16;" :: "r"(saddr), "l"(g));
}

__device__ __forceinline__ uint32_t f2tf32(float x) {
    uint32_t u;
    asm("cvt.rna.tf32.f32 %0, %1;" : "=r"(u) : "f"(x));
    return u;
}

__device__ __forceinline__ uint32_t packh2(float lo, float hi) {
    __half2 h = __floats2half2_rn(lo, hi);
    return *(uint32_t*)&h;
}

__device__ __forceinline__ void mma_tf32(float* d, const uint32_t* a, const uint32_t* b) {
    asm volatile(
        "mma.sync.aligned.m16n8k8.row.col.f32.tf32.tf32.f32 "
        "{%0,%1,%2,%3}, {%4,%5,%6,%7}, {%8,%9}, {%0,%1,%2,%3};"
        : "+f"(d[0]), "+f"(d[1]), "+f"(d[2]), "+f"(d[3])
        : "r"(a[0]), "r"(a[1]), "r"(a[2]), "r"(a[3]), "r"(b[0]), "r"(b[1]));
}

__device__ __forceinline__ void mma_f16(float* d, const uint32_t* a, const uint32_t* b) {
    asm volatile(
        "mma.sync.aligned.m16n8k16.row.col.f32.f16.f16.f32 "
        "{%0,%1,%2,%3}, {%4,%5,%6,%7}, {%8,%9}, {%0,%1,%2,%3};"
        : "+f"(d[0]), "+f"(d[1]), "+f"(d[2]), "+f"(d[3])
        : "r"(a[0]), "r"(a[1]), "r"(a[2]), "r"(a[3]), "r"(b[0]), "r"(b[1]));
}

__device__ __forceinline__ int pposu(int j) { return (j < 4) ? 2 * j : 2 * (j - 4) + 1; }

// ============================================================================
// K0a: transpose + u32-permute + fp16 convert of ALL 4 weights (blockIdx.z)
// ============================================================================
__global__ __launch_bounds__(256) void transpose_fp16_all_k(
    const float* __restrict__ Wq, const float* __restrict__ Wk,
    const float* __restrict__ Wv, const float* __restrict__ Wo,
    uint32_t* __restrict__ WthBase)
{
    __shared__ float t[32][33];
    int z = blockIdx.z;
    const float* W = (z == 0) ? Wq : (z == 1) ? Wk : (z == 2) ? Wv : Wo;
    uint32_t* Wth = WthBase + (size_t)z * EMBD * EMBD_U;
    int bx = blockIdx.x * 32, by = blockIdx.y * 32;
    int txx = threadIdx.x;
    for (int i = threadIdx.y; i < 32; i += 8)
        t[i][txx] = W[(size_t)(by + i) * EMBD + bx + txx];
    __syncthreads();
    if (txx < 16) {
        int j = txx & 7;
        int pos = (by >> 1) + (txx >> 3) * 8 + pposu(j);
        for (int i = threadIdx.y; i < 32; i += 8) {
            uint32_t u = packh2(t[2 * txx][i], t[2 * txx + 1][i]);
            Wth[(size_t)(bx + i) * EMBD_U + pos] = u;
        }
    }
}

// ============================================================================
// K0b: u32-permute + fp16 convert of x
// ============================================================================
__global__ __launch_bounds__(256) void perm_cvt_fp16_k(const float* __restrict__ src,
                                                       uint32_t* __restrict__ dst)
{
    size_t g16 = (size_t)blockIdx.x * 256 + threadIdx.x;
    size_t base = g16 * 16;
    float4 f0 = *(const float4*)&src[base];
    float4 f1 = *(const float4*)&src[base + 4];
    float4 f2 = *(const float4*)&src[base + 8];
    float4 f3 = *(const float4*)&src[base + 12];
    uint4 o0, o1;
    o0.x = packh2(f0.x, f0.y);
    o0.y = packh2(f2.x, f2.y);
    o0.z = packh2(f0.z, f0.w);
    o0.w = packh2(f2.z, f2.w);
    o1.x = packh2(f1.x, f1.y);
    o1.y = packh2(f3.x, f3.y);
    o1.z = packh2(f1.z, f1.w);
    o1.w = packh2(f3.z, f3.w);
    *(uint4*)&dst[g16 * 8] = o0;
    *(uint4*)&dst[g16 * 8 + 4] = o1;
}

// ============================================================================
// K0c: rope cos/sin tables
// ============================================================================
__global__ __launch_bounds__(256) void rope_tab_k(float* __restrict__ cost,
                                                  float* __restrict__ sint)
{
    size_t idx = (size_t)blockIdx.x * 256 + threadIdx.x;
    int t = (int)(idx >> 10);
    int i = (int)(idx & 1023);
    float inv = powf(10000.0f, -(float)(2 * i) * (1.0f / 2048.0f));
    float ang = (float)t * inv;
    cost[idx] = cosf(ang);
    sint[idx] = sinf(ang);
}

// ============================================================================
// K1: fp16 mma.sync GEMM — CTA 128x128x32, 4-stage, 2 CTAs/SM
// ============================================================================
#define BM 128
#define BN 128
#define BK 32
#define BKU 16
#define BKP_U 24
#define NSTG 4
#define STG_U ((BM + BN) * BKP_U)          // 6144 u32 per stage
#define GEMM_SMEM_BYTES (NSTG * STG_U * 4) // 98304

__device__ __forceinline__ void load_stage_h(const uint32_t* __restrict__ A,
                                             const uint32_t* __restrict__ Bt,
                                             int brow, int bcol, int k0u,
                                             uint32_t sA, uint32_t sB, int tid)
{
#pragma unroll
    for (int it = 0; it < 2; it++) {        // A: 128 rows x 4 cp16
        int idx = tid + it * 256;
        int row = idx >> 2, c4 = idx & 3;
        cp16(sA + (row * BKP_U + c4 * 4) * 4,
             A + (size_t)(brow + row) * EMBD_U + k0u + c4 * 4);
    }
#pragma unroll
    for (int it = 0; it < 2; it++) {        // B: 128 rows x 4 cp16
        int idx = tid + it * 256;
        int row = idx >> 2, c4 = idx & 3;
        cp16(sB + (row * BKP_U + c4 * 4) * 4,
             Bt + (size_t)(bcol + row) * EMBD_U + k0u + c4 * 4);
    }
    asm volatile("cp.async.commit_group;" ::: "memory");
}

__device__ __forceinline__ void gemm_mainloop(
    const uint32_t* __restrict__ A, const uint32_t* __restrict__ Bt,
    uint32_t* dsm_u, float acc[4][4][4], int brow, int bcol,
    int tid, int wm, int wn, int lr, int lc)
{
    uint32_t sbase = smem_u32(dsm_u);
    uint32_t sA[NSTG], sB[NSTG];
#pragma unroll
    for (int s = 0; s < NSTG; s++) {
        sA[s] = sbase + s * STG_U * 4;
        sB[s] = sA[s] + BM * BKP_U * 4;
    }

    // prologue: commit NSTG-1 = 3 stages
    load_stage_h(A, Bt, brow, bcol, 0 * BKU, sA[0], sB[0], tid);
    load_stage_h(A, Bt, brow, bcol, 1 * BKU, sA[1], sB[1], tid);
    load_stage_h(A, Bt, brow, bcol, 2 * BKU, sA[2], sB[2], tid);

    const int NIT = EMBD / BK; // 64
    for (int it = 0; it < NIT; it++) {
        if (it < NIT - 2)       asm volatile("cp.async.wait_group 2;" ::: "memory");
        else if (it == NIT - 2) asm volatile("cp.async.wait_group 1;" ::: "memory");
        else                    asm volatile("cp.async.wait_group 0;" ::: "memory");
        __syncthreads();

        // issue stage it+3 before compute (overlaps with MMA)
        if (it + 3 < NIT) {
            int sn = (it + 3) % NSTG;
            load_stage_h(A, Bt, brow, bcol, (it + 3) * BKU, sA[sn], sB[sn], tid);
        }

        int s = it % NSTG;
        const uint32_t* As = dsm_u + (size_t)s * STG_U;
        const uint32_t* Bs = As + BM * BKP_U;

#pragma unroll
        for (int kc = 0; kc < 2; kc++) {
            int off = kc * 8 + 2 * lc;
            uint32_t af[4][4], bf[4][2];
#pragma unroll
            for (int mt = 0; mt < 4; mt++) {
                int r = wm + mt * 16 + lr;
                uint2 a0 = *(const uint2*)&As[r * BKP_U + off];
                uint2 a1 = *(const uint2*)&As[(r + 8) * BKP_U + off];
                af[mt][0] = a0.x; af[mt][2] = a0.y;
                af[mt][1] = a1.x; af[mt][3] = a1.y;
            }
#pragma unroll
            for (int nt = 0; nt < 4; nt++) {
                int cN = wn + nt * 8 + lr;
                uint2 b = *(const uint2*)&Bs[cN * BKP_U + off];
                bf[nt][0] = b.x; bf[nt][1] = b.y;
            }
#pragma unroll
            for (int mt = 0; mt < 4; mt++)
#pragma unroll
                for (int nt = 0; nt < 4; nt++)
                    mma_f16(acc[mt][nt], af[mt], bf[nt]);
        }
        // no trailing sync: next top-of-loop barrier covers the WAR hazard
    }
}

// final GEMM: fp32 output + bias
__global__ __launch_bounds__(256, 2) void gemm_mma_k(
    const uint32_t* __restrict__ A, const uint32_t* __restrict__ Bt,
    const float* __restrict__ bias, float* __restrict__ C)
{
    extern __shared__ uint32_t dsm_u[];
    const int tid = threadIdx.x;
    const int wid = tid >> 5;
    const int lane = tid & 31;
    const int lr = lane >> 2, lc = lane & 3;
    const int wm = (wid >> 2) * 64, wn = (wid & 3) * 32;
    int brow = blockIdx.y * BM, bcol = blockIdx.x * BN;

    float acc[4][4][4];
#pragma unroll
    for (int mt = 0; mt < 4; mt++)
#pragma unroll
        for (int nt = 0; nt < 4; nt++)
#pragma unroll
            for (int r = 0; r < 4; r++) acc[mt][nt][r] = 0.f;

    gemm_mainloop(A, Bt, dsm_u, acc, brow, bcol, tid, wm, wn, lr, lc);

#pragma unroll
    for (int nt = 0; nt < 4; nt++) {
        int col = bcol + wn + nt * 8 + 2 * lc;
        float b0 = bias[col], b1 = bias[col + 1];
#pragma unroll
        for (int mt = 0; mt < 4; mt++) {
            int row = brow + wm + mt * 16 + lr;
            float2 v0 = make_float2(acc[mt][nt][0] + b0, acc[mt][nt][1] + b1);
            float2 v1 = make_float2(acc[mt][nt][2] + b0, acc[mt][nt][3] + b1);
            *(float2*)&C[(size_t)row * EMBD + col] = v0;
            *(float2*)&C[(size_t)(row + 8) * EMBD + col] = v1;
        }
    }
}

// QKV GEMM: fused bias + rope (z<2) + fp16 pack
__global__ __launch_bounds__(256, 2) void gemm_qkv_k(
    const uint32_t* __restrict__ A, const uint32_t* __restrict__ WtBase,
    const float* __restrict__ bq, const float* __restrict__ bk,
    const float* __restrict__ bv,
    uint32_t* __restrict__ qh, uint32_t* __restrict__ kh, uint32_t* __restrict__ vh,
    const float* __restrict__ cost, const float* __restrict__ sint)
{
    extern __shared__ uint32_t dsm_u[];
    const int tid = threadIdx.x;
    const int wid = tid >> 5;
    const int lane = tid & 31;
    const int lr = lane >> 2, lc = lane & 3;
    const int wm = (wid >> 2) * 64, wn = (wid & 3) * 32;
    int brow = blockIdx.y * BM, bcol = blockIdx.x * BN;

    int z = blockIdx.z;
    const uint32_t* Bt = WtBase + (size_t)z * EMBD * EMBD_U;
    const float* bias = (z == 0) ? bq : (z == 1) ? bk : bv;
    uint32_t* Ch = (z == 0) ? qh : (z == 1) ? kh : vh;
    bool dorope = (z < 2);

    float acc[4][4][4];
#pragma unroll
    for (int mt = 0; mt < 4; mt++)
#pragma unroll
        for (int nt = 0; nt < 4; nt++)
#pragma unroll
            for (int r = 0; r < 4; r++) acc[mt][nt][r] = 0.f;

    gemm_mainloop(A, Bt, dsm_u, acc, brow, bcol, tid, wm, wn, lr, lc);

#pragma unroll
    for (int nt = 0; nt < 4; nt++) {
        int col = bcol + wn + nt * 8 + 2 * lc;
        int pi = col >> 1;
        float b0 = bias[col], b1 = bias[col + 1];
#pragma unroll
        for (int mt = 0; mt < 4; mt++) {
#pragma unroll
            for (int h = 0; h < 2; h++) {
                int row = brow + wm + mt * 16 + lr + h * 8;
                float a0 = acc[mt][nt][2 * h + 0] + b0;
                float a1 = acc[mt][nt][2 * h + 1] + b1;
                if (dorope) {
                    int t = row & (SEQ - 1);
                    float c = cost[(size_t)t * 1024 + pi];
                    float s = sint[(size_t)t * 1024 + pi];
                    float r0 = a0 * c - a1 * s;
                    float r1 = a0 * s + a1 * c;
                    a0 = r0; a1 = r1;
                }
                Ch[(size_t)row * EMBD_U + pi] = packh2(a0, a1);
            }
        }
    }
}

// ============================================================================
// K2b: merged v^T / sk^T transposes (blockIdx.y parity selects path)
// ============================================================================
__global__ __launch_bounds__(256) void vtskt_k(const uint32_t* __restrict__ vh,
                                               const uint32_t* __restrict__ kh,
                                               uint32_t* __restrict__ vth,
                                               uint32_t* __restrict__ skth)
{
    __shared__ float t[32][68];
    int bhs = blockIdx.z;
    int p0 = blockIdx.x * 32;
    int which = blockIdx.y & 1;               // 0 = v, 1 = sk
    int l0 = (blockIdx.y >> 1) * 32;
    const uint32_t* seg = (which ? kh : vh) + ((size_t)bhs << 15);
    uint32_t* dst = (which ? skth : vth) + (size_t)bhs * DHEAD * SEGL_U;
    int txx = threadIdx.x, ty = threadIdx.y;
    for (int i = ty; i < 32; i += 8) {
        __half2 h = *(const __half2*)&seg[(size_t)(l0 + i) * 64 + p0 + txx];
        t[i][2 * txx] = __low2float(h);
        t[i][2 * txx + 1] = __high2float(h);
    }
    __syncthreads();
    int tid = ty * 32 + txx;
#pragma unroll
    for (int j = 0; j < 4; j++) {
        int flat = tid + j * 256;
        int d = flat >> 4, c = flat & 15;
        float a = t[2 * c][d], b = t[2 * c + 1][d];
        if (which) { a = elu1(a); b = elu1(b); }
        dst[(size_t)(2 * p0 + d) * SEGL_U + (l0 >> 1) + c] = packh2(a, b);
    }
}

// ============================================================================
// K2d: Zseg[bhs][d] = row-sum of skth
// ============================================================================
__global__ __launch_bounds__(256) void zsum_k(const uint32_t* __restrict__ skth,
                                              float* __restrict__ Zseg)
{
    int bhs = blockIdx.x;
    int tid = threadIdx.x;
    int d = tid >> 1;
    int half = tid & 1;
    const uint32_t* row = skth + (size_t)bhs * DHEAD * SEGL_U
                        + (size_t)d * SEGL_U + half * 128;
    float s = 0.f;
#pragma unroll 16
    for (int j = 0; j < 128; j++) {
        __half2 h = *(const __half2*)&row[j];
        s += __low2float(h) + __high2float(h);
    }
    s += __shfl_xor_sync(0xffffffffu, s, 1);
    if (half == 0) Zseg[bhs * DHEAD + d] = s;
}

// ============================================================================
// K3: FUSED flash attention + A_mem + combine, with pipelined k/v prefetch
// ============================================================================
#define SCP 68
#define AMP 136
#define FAM_U32 (43520 + 1536)
#define FAM_SMEM_BYTES (FAM_U32 * 4)   // 180224

__global__ __launch_bounds__(256, 1) void fam_k(
    const uint32_t* __restrict__ qh, const uint32_t* __restrict__ kh,
    const uint32_t* __restrict__ vth, const float* __restrict__ memsegT,
    const float* __restrict__ Zseg, const float* __restrict__ beta,
    uint32_t* __restrict__ attnh)
{
    extern __shared__ uint32_t smu[];
    uint32_t* qs = smu;
    uint32_t* ks = smu + 128 * SCP;
    uint32_t* Ps = smu + 2 * 128 * SCP;
    uint32_t* vsb[2] = { smu + 3 * 128 * SCP, smu + 4 * 128 * SCP };
    uint32_t* aq = smu + 128 * SCP;
    uint32_t* ms = smu + 3 * 128 * SCP;
    float* pmax = (float*)(smu + 43520);
    float* psum = pmax + 4 * 128;
    float* m_s = psum + 4 * 128;
    float* f_s = m_s + 128;
    float* ssum_s = f_s + 128;
    float* Zs = ssum_s + 128;

    uint32_t sq = smem_u32(qs);
    uint32_t sk = smem_u32(ks);
    uint32_t sv0 = smem_u32(vsb[0]);
    uint32_t sv1 = smem_u32(vsb[1]);
    uint32_t smb = smem_u32(ms);

    const float scale = 0.08838834764831845f;
    const int tid = threadIdx.x;
    const int wid = tid >> 5;
    const int lane = tid & 31;
    const int lr = lane >> 2;
    const int lc = lane & 3;
    const int wm = (wid >> 2) * 64;
    const int wn = (wid & 3) * 32;
    const int wci = wid & 3;

    int bhs = blockIdx.y;
    int l0 = blockIdx.x * 128;
    size_t segbase_u = ((size_t)bhs) << 15;
    const uint32_t* qseg = qh + segbase_u;
    const uint32_t* kseg = kh + segbase_u;
    const uint32_t* vtseg = vth + (size_t)bhs * DHEAD * SEGL_U;
    const float* memb = memsegT + (size_t)bhs * DHEAD * DHEAD;
    float g = 1.0f / (1.0f + expf(-beta[0]));
    float gm1 = 1.0f - g;

#pragma unroll
    for (int it = 0; it < 8; it++) {
        int idx = tid + it * 256;
        int row = idx >> 4, c4 = idx & 15;
        cp16(sq + (row * SCP + c4 * 4) * 4,
             qseg + (size_t)(l0 + row) * 64 + c4 * 4);
    }
#pragma unroll
    for (int it = 0; it < 8; it++) {
        int idx = tid + it * 256;
        int row = idx >> 4, c4 = idx & 15;
        cp16(sk + (row * SCP + c4 * 4) * 4,
             kseg + (size_t)row * 64 + c4 * 4);
    }
#pragma unroll
    for (int it = 0; it < 8; it++) {
        int idx = tid + it * 256;
        int row = idx >> 4, c4 = idx & 15;
        cp16(sv0 + (row * SCP + c4 * 4) * 4,
             vtseg + (size_t)row * SEGL_U + c4 * 4);
    }
    asm volatile("cp.async.commit_group;" ::: "memory");

    if (tid < 128) { m_s[tid] = -1e30f; ssum_s[tid] = 0.f; }

    float Oacc[4][4][4];
#pragma unroll
    for (int mt = 0; mt < 4; mt++)
#pragma unroll
        for (int nt = 0; nt < 4; nt++)
#pragma unroll
            for (int r = 0; r < 4; r++) Oacc[mt][nt][r] = 0.f;

    for (int kt = 0; kt < 4; kt++) {
        uint32_t* vs = vsb[kt & 1];
        asm volatile("cp.async.wait_group 0;" ::: "memory");
        __syncthreads();

        float Sacc[4][4][4];
#pragma unroll
        for (int mt = 0; mt < 4; mt++)
#pragma unroll
            for (int nt = 0; nt < 4; nt++)
#pragma unroll
                for (int r = 0; r < 4; r++) Sacc[mt][nt][r] = 0.f;

#pragma unroll
        for (int kb = 0; kb < 64; kb += 8) {
            uint32_t af[4][4], bf[4][2];
#pragma unroll
            for (int mt = 0; mt < 4; mt++) {
                int r = wm + mt * 16 + lr;
                af[mt][0] = qs[r * SCP + kb + lc];
                af[mt][1] = qs[(r + 8) * SCP + kb + lc];
                af[mt][2] = qs[r * SCP + kb + lc + 4];
                af[mt][3] = qs[(r + 8) * SCP + kb + lc + 4];
            }
#pragma unroll
            for (int nt = 0; nt < 4; nt++) {
                int cN = wn + nt * 8 + lr;
                bf[nt][0] = ks[cN * SCP + kb + lc];
                bf[nt][1] = ks[cN * SCP + kb + lc + 4];
            }
#pragma unroll
            for (int mt = 0; mt < 4; mt++)
#pragma unroll
                for (int nt = 0; nt < 4; nt++)
                    mma_f16(Sacc[mt][nt], af[mt], bf[nt]);
        }
#pragma unroll
        for (int mt = 0; mt < 4; mt++)
#pragma unroll
            for (int nt = 0; nt < 4; nt++)
#pragma unroll
                for (int r = 0; r < 4; r++) Sacc[mt][nt][r] *= scale;

#pragma unroll
        for (int mt = 0; mt < 4; mt++) {
#pragma unroll
            for (int h = 0; h < 2; h++) {
                float mv = -1e30f;
#pragma unroll
                for (int nt = 0; nt < 4; nt++) {
                    mv = fmaxf(mv, Sacc[mt][nt][2 * h]);
                    mv = fmaxf(mv, Sacc[mt][nt][2 * h + 1]);
                }
                mv = fmaxf(mv, __shfl_xor_sync(0xffffffffu, mv, 1));
                mv = fmaxf(mv, __shfl_xor_sync(0xffffffffu, mv, 2));
                if (lc == 0) pmax[wci * 128 + wm + mt * 16 + lr + h * 8] = mv;
            }
        }
        __syncthreads();
        if (kt < 3) {
            uint32_t svn = (kt & 1) ? sv0 : sv1;
#pragma unroll
            for (int it = 0; it < 8; it++) {
                int idx = tid + it * 256;
                int row = idx >> 4, c4 = idx & 15;
                cp16(sk + (row * SCP + c4 * 4) * 4,
                     kseg + (size_t)((kt + 1) * 128 + row) * 64 + c4 * 4);
            }
#pragma unroll
            for (int it = 0; it < 8; it++) {
                int idx = tid + it * 256;
                int row = idx >> 4, c4 = idx & 15;
                cp16(svn + (row * SCP + c4 * 4) * 4,
                     vtseg + (size_t)row * SEGL_U + (kt + 1) * 64 + c4 * 4);
            }
            asm volatile("cp.async.commit_group;" ::: "memory");
        }

        if (tid < 128) {
            float mo = m_s[tid];
            float nm = fmaxf(fmaxf(pmax[tid], pmax[128 + tid]),
                             fmaxf(pmax[256 + tid], pmax[384 + tid]));
            float mn = fmaxf(mo, nm);
            float f = expf(mo - mn);
            m_s[tid] = mn;
            f_s[tid] = f;
            ssum_s[tid] *= f;
        }
        __syncthreads();

#pragma unroll
        for (int mt = 0; mt < 4; mt++) {
#pragma unroll
            for (int h = 0; h < 2; h++) {
                int row = wm + mt * 16 + lr + h * 8;
                float m = m_s[row];
                float f = f_s[row];
                float rsum = 0.f;
#pragma unroll
                for (int nt = 0; nt < 4; nt++) {
                    float p0 = expf(Sacc[mt][nt][2 * h] - m);
                    float p1 = expf(Sacc[mt][nt][2 * h + 1] - m);
                    rsum += p0 + p1;
                    Ps[row * SCP + (wn >> 1) + nt * 4 + lc] = packh2(p0, p1);
                    Oacc[mt][nt][2 * h] *= f;
                    Oacc[mt][nt][2 * h + 1] *= f;
                }
                rsum += __shfl_xor_sync(0xffffffffu, rsum, 1);
                rsum += __shfl_xor_sync(0xffffffffu, rsum, 2);
                if (lc == 0) psum[wci * 128 + row] = rsum;
            }
        }
        __syncthreads();

        if (tid < 128)
            ssum_s[tid] += psum[tid] + psum[128 + tid] + psum[256 + tid] + psum[384 + tid];

#pragma unroll
        for (int kb = 0; kb < 64; kb += 8) {
            uint32_t af[4][4], bf[4][2];
#pragma unroll
            for (int mt = 0; mt < 4; mt++) {
                int r = wm + mt * 16 + lr;
                af[mt][0] = Ps[r * SCP + kb + lc];
                af[mt][1] = Ps[(r + 8) * SCP + kb + lc];
                af[mt][2] = Ps[r * SCP + kb + lc + 4];
                af[mt][3] = Ps[(r + 8) * SCP + kb + lc + 4];
            }
#pragma unroll
            for (int nt = 0; nt < 4; nt++) {
                int cN = wn + nt * 8 + lr;
                bf[nt][0] = vs[cN * SCP + kb + lc];
                bf[nt][1] = vs[cN * SCP + kb + lc + 4];
            }
#pragma unroll
            for (int mt = 0; mt < 4; mt++)
#pragma unroll
                for (int nt = 0; nt < 4; nt++)
                    mma_f16(Oacc[mt][nt], af[mt], bf[nt]);
        }
        __syncthreads();
    }

    // ---------------- amem phase ----------------
#pragma unroll
    for (int it = 0; it < 16; it++) {
        int idx = tid + it * 256;
        int row = idx >> 5, c4 = idx & 31;
        cp16(smb + (row * AMP + c4 * 4) * 4,
             memb + (size_t)row * DHEAD + c4 * 4);
    }
    asm volatile("cp.async.commit_group;" ::: "memory");

#pragma unroll
    for (int it = 0; it < 32; it++) {
        int flat = it * 256 + tid;
        int row = flat >> 6, col = flat & 63;
        __half2 h = *(const __half2*)&qs[row * SCP + col];
        aq[row * AMP + 2 * col]     = f2tf32(elu1(__low2float(h)));
        aq[row * AMP + 2 * col + 1] = f2tf32(elu1(__high2float(h)));
    }
    asm volatile("cp.async.wait_group 0;" ::: "memory");
    __syncthreads();

    {
        int r = tid >> 1;
        int half = (tid & 1) * 64;
        float partial = 0.f;
#pragma unroll 16
        for (int j = 0; j < 64; j++)
            partial += __uint_as_float(aq[r * AMP + half + j]);
        partial += __shfl_xor_sync(0xffffffffu, partial, 1);
        if ((tid & 1) == 0) pmax[r] = partial;
#pragma unroll 16
        for (int j = 0; j < 64; j++) {
            uint32_t* p = &ms[r * AMP + half + j];
            *p = f2tf32(__uint_as_float(*p));
        }
    }
    if (tid < 128) Zs[tid] = Zseg[bhs * DHEAD + tid];
    __syncthreads();

    float acc[4][4][4];
#pragma unroll
    for (int mt = 0; mt < 4; mt++)
#pragma unroll
        for (int nt = 0; nt < 4; nt++)
#pragma unroll
            for (int r = 0; r < 4; r++) acc[mt][nt][r] = 0.f;

#pragma unroll
    for (int kb = 0; kb < 128; kb += 8) {
        uint32_t af[4][4], bf[4][2];
#pragma unroll
        for (int mt = 0; mt < 4; mt++) {
            int r = wm + mt * 16 + lr;
            af[mt][0] = aq[r * AMP + kb + lc];
            af[mt][1] = aq[(r + 8) * AMP + kb + lc];
            af[mt][2] = aq[r * AMP + kb + lc + 4];
            af[mt][3] = aq[(r + 8) * AMP + kb + lc + 4];
        }
#pragma unroll
        for (int nt = 0; nt < 4; nt++) {
            int cN = wn + nt * 8 + lr;
            bf[nt][0] = ms[cN * AMP + kb + lc];
            bf[nt][1] = ms[cN * AMP + kb + lc + 4];
        }
#pragma unroll
        for (int mt = 0; mt < 4; mt++)
#pragma unroll
            for (int nt = 0; nt < 4; nt++)
                mma_tf32(acc[mt][nt], af[mt], bf[nt]);
    }

#pragma unroll
    for (int nt = 0; nt < 4; nt++) {
        int col = wn + nt * 8 + 2 * lc;
        int j = (col & 15) >> 1;
        int pos = (col >> 4) * 8 + pposu(j);
        float Z0 = Zs[col], Z1 = Zs[col + 1];
#pragma unroll
        for (int mt = 0; mt < 4; mt++) {
#pragma unroll
            for (int h = 0; h < 2; h++) {
                int rloc = wm + mt * 16 + lr + h * 8;
                int row = l0 + rloc;
                float rs = pmax[rloc];
                float sc = gm1 / ssum_s[rloc];
                float a0 = g * acc[mt][nt][2 * h + 0] / (rs * Z0 + 1e-6f)
                         + Oacc[mt][nt][2 * h + 0] * sc;
                float a1 = g * acc[mt][nt][2 * h + 1] / (rs * Z1 + 1e-6f)
                         + Oacc[mt][nt][2 * h + 1] * sc;
                attnh[segbase_u + (size_t)row * (DHEAD / 2) + pos] = packh2(a0, a1);
            }
        }
    }
}

// ============================================================================
// K6: tensorized outer products: memT[e][d] = sum_l v[l][e] * sk[l][d]
// ============================================================================
#define PVP 36
#define OUTER_SMEM_BYTES (2 * 2 * 128 * PVP * 4)

__global__ __launch_bounds__(256) void outer_mma_k(
    const uint32_t* __restrict__ vth, const uint32_t* __restrict__ skth,
    float* __restrict__ memsegT)
{
    extern __shared__ uint32_t smu[];
    uint32_t* Ash = smu;
    uint32_t* Bsh = smu + 2 * 128 * PVP;
    uint32_t sAu = smem_u32(Ash);
    uint32_t sBu = smem_u32(Bsh);

    const int tid = threadIdx.x;
    const int wid = tid >> 5;
    const int lane = tid & 31;
    const int lr = lane >> 2;
    const int lc = lane & 3;
    const int wm = (wid >> 2) * 64;
    const int wn = (wid & 3) * 32;

    int bhs = blockIdx.x;
    const uint32_t* vtseg = vth + (size_t)bhs * DHEAD * SEGL_U;
    const uint32_t* sktseg = skth + (size_t)bhs * DHEAD * SEGL_U;

    float acc[4][4][4];
#pragma unroll
    for (int mt = 0; mt < 4; mt++)
#pragma unroll
        for (int nt = 0; nt < 4; nt++)
#pragma unroll
            for (int r = 0; r < 4; r++) acc[mt][nt][r] = 0.f;

    auto load_st = [&](int k0u, uint32_t sA, uint32_t sB) {
#pragma unroll
        for (int it = 0; it < 4; it++) {
            int idx = tid + it * 256;
            int row = idx >> 3, c4 = idx & 7;
            cp16(sA + (row * PVP + c4 * 4) * 4,
                 vtseg + (size_t)row * SEGL_U + k0u + c4 * 4);
        }
#pragma unroll
        for (int it = 0; it < 4; it++) {
            int idx = tid + it * 256;
            int row = idx >> 3, c4 = idx & 7;
            cp16(sB + (row * PVP + c4 * 4) * 4,
                 sktseg + (size_t)row * SEGL_U + k0u + c4 * 4);
        }
        asm volatile("cp.async.commit_group;" ::: "memory");
    };

    load_st(0, sAu, sBu);
    load_st(32, sAu + 128 * PVP * 4, sBu + 128 * PVP * 4);

    const int NIT = SEGL_U / 32;
    for (int it = 0; it < NIT; it++) {
        int s = it & 1;
        if (it == NIT - 1) asm volatile("cp.async.wait_group 0;" ::: "memory");
        else               asm volatile("cp.async.wait_group 1;" ::: "memory");
        __syncthreads();

        const uint32_t* As = Ash + s * 128 * PVP;
        const uint32_t* Bs = Bsh + s * 128 * PVP;
#pragma unroll
        for (int kb = 0; kb < 32; kb += 8) {
            uint32_t af[4][4], bf[4][2];
#pragma unroll
            for (int mt = 0; mt < 4; mt++) {
                int r = wm + mt * 16 + lr;
                af[mt][0] = As[r * PVP + kb + lc];
                af[mt][1] = As[(r + 8) * PVP + kb + lc];
                af[mt][2] = As[r * PVP + kb + lc + 4];
                af[mt][3] = As[(r + 8) * PVP + kb + lc + 4];
            }
#pragma unroll
            for (int nt = 0; nt < 4; nt++) {
                int cN = wn + nt * 8 + lr;
                bf[nt][0] = Bs[cN * PVP + kb + lc];
                bf[nt][1] = Bs[cN * PVP + kb + lc + 4];
            }
#pragma unroll
            for (int mt = 0; mt < 4; mt++)
#pragma unroll
                for (int nt = 0; nt < 4; nt++)
                    mma_f16(acc[mt][nt], af[mt], bf[nt]);
        }
        __syncthreads();
        if (it + 2 < NIT)
            load_st((it + 2) * 32, sAu + s * 128 * PVP * 4, sBu + s * 128 * PVP * 4);
    }

    float* memb = memsegT + (size_t)bhs * DHEAD * DHEAD;
#pragma unroll
    for (int nt = 0; nt < 4; nt++) {
        int col = wn + nt * 8 + 2 * lc;
#pragma unroll
        for (int mt = 0; mt < 4; mt++) {
            int row = wm + mt * 16 + lr;
            *(float2*)&memb[(size_t)row * DHEAD + col] =
                make_float2(acc[mt][nt][0], acc[mt][nt][1]);
            *(float2*)&memb[(size_t)(row + 8) * DHEAD + col] =
                make_float2(acc[mt][nt][2], acc[mt][nt][3]);
        }
    }
}

// ============================================================================
// K7: in-place exclusive prefix over the 8 segments
// ============================================================================
__global__ __launch_bounds__(256) void prefix_mem_k(float* __restrict__ memseg)
{
    size_t idx = (size_t)blockIdx.x * 256 + threadIdx.x;
    int bh = (int)(idx >> 14);
    int off = (int)(idx & 16383);
    size_t base = ((size_t)bh * NSEG) * 16384 + off;
    float run = 0.f;
#pragma unroll
    for (int s = 0; s < NSEG; s++) {
        float t = memseg[base + (size_t)s * 16384];
        memseg[base + (size_t)s * 16384] = run;
        run += t;
    }
}

__global__ __launch_bounds__(256) void prefix_Z_k(float* __restrict__ Zseg)
{
    int idx = blockIdx.x * 256 + threadIdx.x;
    int bh = idx >> 7;
    int d = idx & 127;
    int base = bh * NSEG * DHEAD + d;
    float run = 0.f;
#pragma unroll
    for (int s = 0; s < NSEG; s++) {
        float t = Zseg[base + s * DHEAD];
        Zseg[base + s * DHEAD] = run;
        run += t;
    }
}

// ============================================================================
// Host launch
// ============================================================================
extern "C" void kernel_launch(void* const* d_in, const int* in_sizes, int n_in,
                              void* d_out, int out_size)
{
    (void)in_sizes; (void)n_in; (void)out_size;
    const float* x    = (const float*)d_in[0];
    const float* Wq   = (const float*)d_in[1];
    const float* bq   = (const float*)d_in[2];
    const float* Wk   = (const float*)d_in[3];
    const float* bk   = (const float*)d_in[4];
    const float* Wv   = (const float*)d_in[5];
    const float* bv   = (const float*)d_in[6];
    const float* Wo   = (const float*)d_in[7];
    const float* bo   = (const float*)d_in[8];
    const float* beta = (const float*)d_in[9];
    float* out = (float*)d_out;

    static float *pmemsegT = nullptr, *pZseg = nullptr, *pcost = nullptr, *psint = nullptr;
    static uint32_t *pWth = nullptr, *pxh = nullptr, *pattnh = nullptr,
                    *pqh = nullptr, *pkh = nullptr, *pvh = nullptr,
                    *pvth = nullptr, *pskth = nullptr;
    if (!pWth) {
        cudaGetSymbolAddress((void**)&pmemsegT, g_memsegT);
        cudaGetSymbolAddress((void**)&pZseg, g_Zseg);
        cudaGetSymbolAddress((void**)&pWth, g_Wth);
        cudaGetSymbolAddress((void**)&pxh, g_xh);
        cudaGetSymbolAddress((void**)&pattnh, g_attnh);
        cudaGetSymbolAddress((void**)&pqh, g_qh);
        cudaGetSymbolAddress((void**)&pkh, g_kh);
        cudaGetSymbolAddress((void**)&pvh, g_vh);
        cudaGetSymbolAddress((void**)&pvth, g_vth);
        cudaGetSymbolAddress((void**)&pskth, g_skth);
        cudaGetSymbolAddress((void**)&pcost, g_cost);
        cudaGetSymbolAddress((void**)&psint, g_sint);
        cudaFuncSetAttribute(gemm_mma_k, cudaFuncAttributeMaxDynamicSharedMemorySize,
                             GEMM_SMEM_BYTES);
        cudaFuncSetAttribute(gemm_qkv_k, cudaFuncAttributeMaxDynamicSharedMemorySize,
                             GEMM_SMEM_BYTES);
        cudaFuncSetAttribute(fam_k, cudaFuncAttributeMaxDynamicSharedMemorySize,
                             FAM_SMEM_BYTES);
        cudaFuncSetAttribute(outer_mma_k, cudaFuncAttributeMaxDynamicSharedMemorySize,
                             OUTER_SMEM_BYTES);
    }

    const size_t WSZ_U = (size_t)EMBD * EMBD_U;
    dim3 tblk(32, 8);
    transpose_fp16_all_k<<<dim3(EMBD / 32, EMBD / 32, 4), tblk>>>(Wq, Wk, Wv, Wo, pWth);

    perm_cvt_fp16_k<<<(int)(TOTAL / 16 / 256), 256>>>(x, pxh);
    rope_tab_k<<<(SEQ * 1024) / 256, 256>>>(pcost, psint);

    // QKV GEMM with fused rope + fp16 pack (128x128 tile, 2 CTAs/SM)
    dim3 qkvgrid(EMBD / BN, MTOK / BM, 3); // (16, 128, 3)
    gemm_qkv_k<<<qkvgrid, 256, GEMM_SMEM_BYTES>>>(pxh, pWth, bq, bk, bv,
                                                  pqh, pkh, pvh, pcost, psint);

    // merged v^T / sk^T transposes
    vtskt_k<<<dim3(2, (SEGL / 32) * 2, NBH * NSEG), tblk>>>(pvh, pkh, pvth, pskth);

    // parallel linear-memory path (tensorized)
    outer_mma_k<<<NBH * NSEG, 256, OUTER_SMEM_BYTES>>>(pvth, pskth, pmemsegT);
    zsum_k<<<NBH * NSEG, 256>>>(pskth, pZseg);
    prefix_mem_k<<<(NBH * 16384) / 256, 256>>>(pmemsegT);
    prefix_Z_k<<<(NBH * DHEAD) / 256, 256>>>(pZseg);

    // fused flash attention + A_mem + combine, fp16-permuted output
    fam_k<<<dim3(SEGL / 128, NBH * NSEG), 256, FAM_SMEM_BYTES>>>(
        pqh, pkh, pvth, pmemsegT, pZseg, beta, pattnh);

    gemm_mma_k<<<dim3(EMBD / BN, MTOK / BM), 256, GEMM_SMEM_BYTES>>>(
        pattnh, pWth + 3 * WSZ_U, bo, out);
}